// round 10
// baseline (speedup 1.0000x reference)
#include <cuda_runtime.h>
#include <cuda_bf16.h>
#include <cstdint>

#define B_   2
#define S_   2048
#define D_   1024
#define H_   16
#define HD_  64
#define M_   (B_*S_)     // 4096
#define G_   (B_*H_)     // 32
#define NE_  ((size_t)M_*D_)   // 4194304

// ---- scratch (static device arrays; no allocation allowed) ----
__device__ __nv_bfloat16 g_xh[NE_], g_xl[NE_];      // x bf16 hi/lo
__device__ __nv_bfloat16 g_wh[NE_], g_wl[NE_];      // wq|wk|wv|wo hi/lo
__device__ __nv_bfloat16 g_qh[NE_], g_ql[NE_];      // Q head layout [g,s,hd]
__device__ __nv_bfloat16 g_kh[NE_], g_kl[NE_];
__device__ __nv_bfloat16 g_vh[NE_], g_vl[NE_];
__device__ float         g_vf[NE_];                 // V fp32 (exclusion)
__device__ __nv_bfloat16 g_obh[NE_], g_obl[NE_];    // attn out [b,s,d]

// ============================================================================
// helpers
// ============================================================================
__device__ __forceinline__ uint32_t smem_u32(const void* p) {
    uint32_t a;
    asm("{ .reg .u64 t; cvta.to.shared.u64 t, %1; cvt.u32.u64 %0, t; }"
        : "=r"(a) : "l"(p));
    return a;
}
__device__ __forceinline__ void ldm_x4(uint32_t* r, uint32_t addr) {
    asm volatile("ldmatrix.sync.aligned.m8n8.x4.shared.b16 {%0,%1,%2,%3}, [%4];"
        : "=r"(r[0]), "=r"(r[1]), "=r"(r[2]), "=r"(r[3]) : "r"(addr));
}
__device__ __forceinline__ void ldm_x4_t(uint32_t* r, uint32_t addr) {
    asm volatile("ldmatrix.sync.aligned.m8n8.x4.trans.shared.b16 {%0,%1,%2,%3}, [%4];"
        : "=r"(r[0]), "=r"(r[1]), "=r"(r[2]), "=r"(r[3]) : "r"(addr));
}
__device__ __forceinline__ void mma16816(float* c, const uint32_t* a,
                                         uint32_t b0, uint32_t b1) {
    asm volatile(
        "mma.sync.aligned.m16n8k16.row.col.f32.bf16.bf16.f32 "
        "{%0,%1,%2,%3}, {%4,%5,%6,%7}, {%8,%9}, {%0,%1,%2,%3};"
        : "+f"(c[0]), "+f"(c[1]), "+f"(c[2]), "+f"(c[3])
        : "r"(a[0]), "r"(a[1]), "r"(a[2]), "r"(a[3]), "r"(b0), "r"(b1));
}
__device__ __forceinline__ uint32_t packbf(float x, float y) {
    __nv_bfloat162 t;
    t.x = __float2bfloat16_rn(x);
    t.y = __float2bfloat16_rn(y);
    return *(uint32_t*)&t;
}
__device__ __forceinline__ uint32_t packbf_lo(float x, float y, uint32_t hi) {
    __nv_bfloat162 h = *(__nv_bfloat162*)&hi;
    return packbf(x - __bfloat162float(h.x), y - __bfloat162float(h.y));
}
__device__ __forceinline__ float fexp2(float x) {
    float y;
    asm("ex2.approx.f32 %0, %1;" : "=f"(y) : "f"(x));
    return y;
}
__device__ __forceinline__ void cpa(uint32_t dst, const void* src) {
    asm volatile("cp.async.cg.shared.global [%0], [%1], 16;"
        :: "r"(dst), "l"(src) : "memory");
}
#define CP_COMMIT() asm volatile("cp.async.commit_group;" ::: "memory")
#define CP_WAIT(n)  asm volatile("cp.async.wait_group %0;" :: "n"(n) : "memory")

// 0.125 (1/sqrt(64)) * log2(e)  -> softmax run in log2 domain
#define SSCALE 0.18033688f

// ============================================================================
// Convert pass: x (4 quarters) + 4 weights -> bf16 hi/lo
// ============================================================================
__global__ void __launch_bounds__(256)
convert_all(const float* __restrict__ x,
            const float* __restrict__ wq, const float* __restrict__ wk,
            const float* __restrict__ wv, const float* __restrict__ wo,
            __nv_bfloat16* __restrict__ xh, __nv_bfloat16* __restrict__ xl,
            __nv_bfloat16* __restrict__ wh, __nv_bfloat16* __restrict__ wl)
{
    const int z = blockIdx.y;
    const float* src;
    __nv_bfloat16 *dh, *dl;
    if (z < 4) {
        src = x  + ((long)z << 20);
        dh  = xh + ((long)z << 20);
        dl  = xl + ((long)z << 20);
    } else {
        const float* ws = (z == 4) ? wq : (z == 5) ? wk : (z == 6) ? wv : wo;
        src = ws;
        dh  = wh + ((long)(z - 4) << 20);
        dl  = wl + ((long)(z - 4) << 20);
    }
    long i = ((long)blockIdx.x * 256 + threadIdx.x) * 8;
    float4 a = *(const float4*)(src + i);
    float4 b = *(const float4*)(src + i + 4);
    uint32_t h0 = packbf(a.x, a.y), h1 = packbf(a.z, a.w);
    uint32_t h2 = packbf(b.x, b.y), h3 = packbf(b.z, b.w);
    uint32_t l0 = packbf_lo(a.x, a.y, h0), l1 = packbf_lo(a.z, a.w, h1);
    uint32_t l2 = packbf_lo(b.x, b.y, h2), l3 = packbf_lo(b.z, b.w, h3);
    *(uint4*)(dh + i) = make_uint4(h0, h1, h2, h3);
    *(uint4*)(dl + i) = make_uint4(l0, l1, l2, l3);
}

// ============================================================================
// bf16 cp.async GEMM: C = A W^T (+bias). BM=128, BN=256, BK=32, 4-stage.
// Warp tile 64x64 (2x4 grid). 1 CTA/SM. Stage = 48 KB
// [Ahi 8K | Alo 8K | Bhi 16K | Blo 16K], smem row 64B, swizzle ch^((row>>1)&3)
// ============================================================================
__device__ __forceinline__ void gemm_issue(
    const __nv_bfloat16* __restrict__ Ah, const __nv_bfloat16* __restrict__ Al,
    const __nv_bfloat16* __restrict__ Wh, const __nv_bfloat16* __restrict__ Wl,
    int m0, int n0, int s, uint32_t sb, int tid)
{
    const int kc = s * 32;
    const uint32_t stb = sb + (uint32_t)((s & 3) * 49152);
    #pragma unroll
    for (int it = 0; it < 12; ++it) {
        int idx = tid + it * 256;          // 0..3071
        const __nv_bfloat16* src;
        uint32_t dst;
        if (idx < 1024) {                  // A: hi then lo
            int hi  = (idx < 512);
            int t   = idx & 511;
            int row = t >> 2, ch = t & 3;
            src = (hi ? Ah : Al) + (long)(m0 + row) * 1024 + kc + ch * 8;
            dst = stb + (hi ? 0u : 8192u) + (uint32_t)(row * 64)
                + (uint32_t)(((ch ^ ((row >> 1) & 3)) << 4));
        } else {                           // B: hi then lo
            int t   = idx - 1024;
            int hi  = (t < 1024);
            int u   = t & 1023;
            int row = u >> 2, ch = u & 3;
            src = (hi ? Wh : Wl) + (long)(n0 + row) * 1024 + kc + ch * 8;
            dst = stb + (hi ? 16384u : 32768u) + (uint32_t)(row * 64)
                + (uint32_t)(((ch ^ ((row >> 1) & 3)) << 4));
        }
        cpa(dst, src);
    }
}

template<int MODE>
__device__ __forceinline__ void gemm_async(
    const __nv_bfloat16* __restrict__ Ah, const __nv_bfloat16* __restrict__ Al,
    const __nv_bfloat16* __restrict__ Wh, const __nv_bfloat16* __restrict__ Wl,
    const float* __restrict__ bias,
    float* __restrict__ Cf,
    __nv_bfloat16* __restrict__ Oh, __nv_bfloat16* __restrict__ Ol,
    float* __restrict__ Of,
    char* smem)
{
    const int tid = threadIdx.x;
    const int wid = tid >> 5;
    const int l   = tid & 31;
    const int m0  = blockIdx.y * 128;
    const int n0  = blockIdx.x * 256;
    const int wm  = (wid >> 2) * 64;      // 2 row groups
    const int wn  = (wid & 3) * 64;       // 4 col groups

    const int aRow = (l & 15);
    const int aCk  = (l >> 4);
    const int bRow = ((l >> 4) & 1) * 8 + (l & 7);
    const int bCk  = (l >> 3) & 1;

    float acc[4][8][4];
    #pragma unroll
    for (int a = 0; a < 4; ++a)
        #pragma unroll
        for (int b = 0; b < 8; ++b)
            #pragma unroll
            for (int c = 0; c < 4; ++c) acc[a][b][c] = 0.0f;

    const uint32_t sb = smem_u32(smem);

    gemm_issue(Ah, Al, Wh, Wl, m0, n0, 0, sb, tid); CP_COMMIT();
    gemm_issue(Ah, Al, Wh, Wl, m0, n0, 1, sb, tid); CP_COMMIT();
    gemm_issue(Ah, Al, Wh, Wl, m0, n0, 2, sb, tid); CP_COMMIT();

    for (int c = 0; c < 32; ++c) {
        if (c < 30) { CP_WAIT(2); } else if (c == 30) { CP_WAIT(1); } else { CP_WAIT(0); }
        __syncthreads();
        if (c + 3 < 32) {
            gemm_issue(Ah, Al, Wh, Wl, m0, n0, c + 3, sb, tid);
            CP_COMMIT();
        }

        const uint32_t stb = sb + (uint32_t)((c & 3) * 49152);
        const uint32_t ahi = stb;
        const uint32_t alo = stb + 8192;
        const uint32_t bhi = stb + 16384;
        const uint32_t blo = stb + 32768;

        #pragma unroll
        for (int ks = 0; ks < 2; ++ks) {
            uint32_t ah[4][4], al[4][4];
            #pragma unroll
            for (int mt = 0; mt < 4; ++mt) {
                int row = wm + mt * 16 + aRow;
                uint32_t off = (uint32_t)(row * 64)
                             + (uint32_t)((((2*ks + aCk) ^ ((row >> 1) & 3)) << 4));
                ldm_x4(ah[mt], ahi + off);
                ldm_x4(al[mt], alo + off);
            }
            #pragma unroll
            for (int nb = 0; nb < 4; ++nb) {
                uint32_t bh[4], bl[4];
                int row = wn + nb * 16 + bRow;
                uint32_t off = (uint32_t)(row * 64)
                             + (uint32_t)((((2*ks + bCk) ^ ((row >> 1) & 3)) << 4));
                ldm_x4(bh, bhi + off);
                ldm_x4(bl, blo + off);
                #pragma unroll
                for (int mt = 0; mt < 4; ++mt) {
                    #pragma unroll
                    for (int nt2 = 0; nt2 < 2; ++nt2) {
                        float* cc = acc[mt][nb * 2 + nt2];
                        mma16816(cc, ah[mt], bh[nt2*2], bh[nt2*2+1]);
                        mma16816(cc, ah[mt], bl[nt2*2], bl[nt2*2+1]);
                        mma16816(cc, al[mt], bh[nt2*2], bh[nt2*2+1]);
                    }
                }
            }
        }
    }

    #pragma unroll
    for (int mt = 0; mt < 4; ++mt) {
        #pragma unroll
        for (int nt = 0; nt < 8; ++nt) {
            int n = n0 + wn + nt * 8 + (l & 3) * 2;
            float2 bb = *(const float2*)(bias + n);
            #pragma unroll
            for (int half = 0; half < 2; ++half) {
                int m = m0 + wm + mt * 16 + (l >> 2) + half * 8;
                float2 r;
                r.x = acc[mt][nt][half*2]   + bb.x;
                r.y = acc[mt][nt][half*2+1] + bb.y;
                if (MODE == 0) {
                    *(float2*)(Cf + (long)m * 1024 + n) = r;
                } else {
                    int b2 = m >> 11, s = m & 2047;
                    int h = n >> 6, hd = n & 63;
                    long addr = ((long)(b2 * H_ + h) * S_ + s) * HD_ + hd;
                    uint32_t hv = packbf(r.x, r.y);
                    *(uint32_t*)(Oh + addr) = hv;
                    *(uint32_t*)(Ol + addr) = packbf_lo(r.x, r.y, hv);
                    if (Of) *(float2*)(Of + addr) = r;
                }
            }
        }
    }
}

__global__ void __launch_bounds__(256, 1)
gemm_qkv(const __nv_bfloat16* __restrict__ xh, const __nv_bfloat16* __restrict__ xl,
         const __nv_bfloat16* __restrict__ wh, const __nv_bfloat16* __restrict__ wl,
         const float* __restrict__ bq, const float* __restrict__ bk,
         const float* __restrict__ bv,
         __nv_bfloat16* __restrict__ qh, __nv_bfloat16* __restrict__ ql,
         __nv_bfloat16* __restrict__ kh, __nv_bfloat16* __restrict__ kl,
         __nv_bfloat16* __restrict__ vh, __nv_bfloat16* __restrict__ vl,
         float* __restrict__ vf)
{
    extern __shared__ char smem[];
    const int z = blockIdx.z;
    const __nv_bfloat16* Wh = wh + ((long)z << 20);
    const __nv_bfloat16* Wl = wl + ((long)z << 20);
    const float* bias = (z == 0) ? bq : (z == 1) ? bk : bv;
    __nv_bfloat16* Oh = (z == 0) ? qh : (z == 1) ? kh : vh;
    __nv_bfloat16* Ol = (z == 0) ? ql : (z == 1) ? kl : vl;
    float* Of = (z == 2) ? vf : nullptr;
    gemm_async<1>(xh, xl, Wh, Wl, bias, nullptr, Oh, Ol, Of, smem);
}

__global__ void __launch_bounds__(256, 1)
gemm_out(const __nv_bfloat16* __restrict__ ah, const __nv_bfloat16* __restrict__ al,
         const __nv_bfloat16* __restrict__ wh, const __nv_bfloat16* __restrict__ wl,
         const float* __restrict__ bias, float* __restrict__ C)
{
    extern __shared__ char smem[];
    gemm_async<0>(ah, al, wh + ((long)3 << 20), wl + ((long)3 << 20),
                  bias, C, nullptr, nullptr, nullptr, smem);
}

// ============================================================================
// Fused attention: Q block 256, warp = 32 Q rows; KV 64-row double-buffered.
// smem: Q hi 32K | Q lo 32K | K 2x16K | V 2x16K = 128 KB. 1 CTA/SM.
// Tiles: 128B rows, swizzle ch^(row&7).
// ============================================================================
__device__ __forceinline__ void issue_q256(const __nv_bfloat16* __restrict__ Gh,
    const __nv_bfloat16* __restrict__ Gl, uint32_t sb, int tid)
{
    #pragma unroll
    for (int it = 0; it < 8; ++it) {
        int idx = tid + it * 256;          // 0..2047
        int row = idx >> 3, ch = idx & 7;
        uint32_t off = (uint32_t)(row * 128) + (uint32_t)(((ch ^ (row & 7)) << 4));
        cpa(sb + off,         Gh + row * 64 + ch * 8);
        cpa(sb + 32768 + off, Gl + row * 64 + ch * 8);
    }
}
__device__ __forceinline__ void issue_kv64(const __nv_bfloat16* __restrict__ Gh,
    const __nv_bfloat16* __restrict__ Gl, uint32_t dst_hi, int tid)
{
    #pragma unroll
    for (int it = 0; it < 2; ++it) {
        int idx = tid + it * 256;          // 0..511
        int row = idx >> 3, ch = idx & 7;
        uint32_t off = (uint32_t)(row * 128) + (uint32_t)(((ch ^ (row & 7)) << 4));
        cpa(dst_hi + off,        Gh + row * 64 + ch * 8);
        cpa(dst_hi + 8192 + off, Gl + row * 64 + ch * 8);
    }
}

__global__ void __launch_bounds__(256, 1)
fused_attn(const __nv_bfloat16* __restrict__ Qh, const __nv_bfloat16* __restrict__ Ql,
           const __nv_bfloat16* __restrict__ Kh, const __nv_bfloat16* __restrict__ Kl,
           const __nv_bfloat16* __restrict__ Vh, const __nv_bfloat16* __restrict__ Vl,
           const float* __restrict__ VF,
           __nv_bfloat16* __restrict__ OBh, __nv_bfloat16* __restrict__ OBl)
{
    extern __shared__ char sm[];
    const int tid = threadIdx.x;
    const int wid = tid >> 5;
    const int l   = tid & 31;
    const int g   = blockIdx.y;
    const int m0  = blockIdx.x * 256;
    const int wm  = wid * 32;

    const long gbase = (long)g * S_ * HD_;
    const __nv_bfloat16* Kgh = Kh + gbase;
    const __nv_bfloat16* Kgl = Kl + gbase;
    const __nv_bfloat16* Vgh = Vh + gbase;
    const __nv_bfloat16* Vgl = Vl + gbase;

    const uint32_t sb = smem_u32(sm);

    // prologue: group 0 = Q + K0 + V0
    issue_q256(Qh + gbase + (long)m0 * HD_, Ql + gbase + (long)m0 * HD_, sb, tid);
    issue_kv64(Kgh, Kgl, sb + 65536, tid);
    issue_kv64(Vgh, Vgl, sb + 98304, tid);
    CP_COMMIT();

    float oacc[16][4];                      // [mt*8 + np*2 + d2][4]
    #pragma unroll
    for (int i = 0; i < 16; ++i)
        #pragma unroll
        for (int j = 0; j < 4; ++j) oacc[i][j] = 0.0f;
    float mrun[2][2], lsum[2][2];           // [mt][half], log2 domain
    #pragma unroll
    for (int a = 0; a < 2; ++a)
        #pragma unroll
        for (int b = 0; b < 2; ++b) { mrun[a][b] = -1e30f; lsum[a][b] = 0.0f; }

    const int aR = (l & 15);
    const int bR = ((l >> 4) & 1) * 8 + (l & 7);
    const int bC = (l >> 3) & 1;
    const int vR = (l & 15);
    const int vC = (l >> 4);

    for (int j = 0; j < 32; ++j) {
        const int cur = j & 1;
        const uint32_t kb = sb + 65536 + cur * 16384;
        const uint32_t vb = sb + 98304 + cur * 16384;

        __syncthreads();   // buffer (j+1)&1 free (consumed in iter j-1)
        if (j + 1 < 32) {
            const int nxt = cur ^ 1;
            issue_kv64(Kgh + (long)(j + 1) * 4096, Kgl + (long)(j + 1) * 4096,
                       sb + 65536 + nxt * 16384, tid);
            issue_kv64(Vgh + (long)(j + 1) * 4096, Vgl + (long)(j + 1) * 4096,
                       sb + 98304 + nxt * 16384, tid);
            CP_COMMIT();
        }
        if (j < 31) { CP_WAIT(1); } else { CP_WAIT(0); }
        __syncthreads();

        // ---- S = Q K^T : warp tile 32 x 64 ----
        float sacc[16][4];                  // [mt*8 + nb*2 + nt2][4]
        #pragma unroll
        for (int i = 0; i < 16; ++i)
            #pragma unroll
            for (int c = 0; c < 4; ++c) sacc[i][c] = 0.0f;

        #pragma unroll
        for (int ks = 0; ks < 4; ++ks) {
            uint32_t ah[2][4], al[2][4];
            #pragma unroll
            for (int mt = 0; mt < 2; ++mt) {
                int row = wm + mt * 16 + aR;
                uint32_t off = (uint32_t)(row * 128)
                             + (uint32_t)((((ks * 2 + (l >> 4)) ^ (row & 7)) << 4));
                ldm_x4(ah[mt], sb + off);
                ldm_x4(al[mt], sb + 32768 + off);
            }
            #pragma unroll
            for (int nb = 0; nb < 4; ++nb) {
                uint32_t bh[4], bl[4];
                int row = nb * 16 + bR;
                uint32_t off = (uint32_t)(row * 128)
                             + (uint32_t)((((ks * 2 + bC) ^ (row & 7)) << 4));
                ldm_x4(bh, kb + off);
                ldm_x4(bl, kb + 8192 + off);
                #pragma unroll
                for (int mt = 0; mt < 2; ++mt) {
                    #pragma unroll
                    for (int nt2 = 0; nt2 < 2; ++nt2) {
                        float* c = sacc[mt * 8 + nb * 2 + nt2];
                        mma16816(c, ah[mt], bh[nt2*2], bh[nt2*2+1]);
                        mma16816(c, ah[mt], bl[nt2*2], bl[nt2*2+1]);
                        mma16816(c, al[mt], bh[nt2*2], bh[nt2*2+1]);
                    }
                }
            }
        }

        // ---- online softmax (log2 domain) ----
        float mnew[2][2] = {{-1e30f, -1e30f}, {-1e30f, -1e30f}};
        #pragma unroll
        for (int mt = 0; mt < 2; ++mt)
            #pragma unroll
            for (int k = 0; k < 8; ++k) {
                float* s = sacc[mt * 8 + k];
                #pragma unroll
                for (int c = 0; c < 4; ++c) s[c] *= SSCALE;
                mnew[mt][0] = fmaxf(mnew[mt][0], fmaxf(s[0], s[1]));
                mnew[mt][1] = fmaxf(mnew[mt][1], fmaxf(s[2], s[3]));
            }
        float corr[2][2];
        #pragma unroll
        for (int mt = 0; mt < 2; ++mt)
            #pragma unroll
            for (int h = 0; h < 2; ++h) {
                float m = mnew[mt][h];
                m = fmaxf(m, __shfl_xor_sync(0xffffffffu, m, 1));
                m = fmaxf(m, __shfl_xor_sync(0xffffffffu, m, 2));
                float mi = fmaxf(mrun[mt][h], m);
                corr[mt][h] = fexp2(mrun[mt][h] - mi);
                mrun[mt][h] = mi;
                lsum[mt][h] *= corr[mt][h];
            }
        float rs[2][2] = {{0.0f, 0.0f}, {0.0f, 0.0f}};
        #pragma unroll
        for (int mt = 0; mt < 2; ++mt)
            #pragma unroll
            for (int k = 0; k < 8; ++k) {
                float* s = sacc[mt * 8 + k];
                s[0] = fexp2(s[0] - mrun[mt][0]);
                s[1] = fexp2(s[1] - mrun[mt][0]);
                s[2] = fexp2(s[2] - mrun[mt][1]);
                s[3] = fexp2(s[3] - mrun[mt][1]);
                rs[mt][0] += s[0] + s[1];
                rs[mt][1] += s[2] + s[3];
            }
        #pragma unroll
        for (int mt = 0; mt < 2; ++mt)
            #pragma unroll
            for (int h = 0; h < 2; ++h) {
                float r = rs[mt][h];
                r += __shfl_xor_sync(0xffffffffu, r, 1);
                r += __shfl_xor_sync(0xffffffffu, r, 2);
                lsum[mt][h] += r;
            }
        #pragma unroll
        for (int mt = 0; mt < 2; ++mt)
            #pragma unroll
            for (int t = 0; t < 8; ++t) {
                float* o = oacc[mt * 8 + t];
                o[0] *= corr[mt][0]; o[1] *= corr[mt][0];
                o[2] *= corr[mt][1]; o[3] *= corr[mt][1];
            }

        // ---- O += P V ----
        #pragma unroll
        for (int kt = 0; kt < 4; ++kt) {
            uint32_t ph[2][4], pl[2][4];
            #pragma unroll
            for (int mt = 0; mt < 2; ++mt) {
                float* s0 = sacc[mt * 8 + kt * 2];
                float* s1 = sacc[mt * 8 + kt * 2 + 1];
                ph[mt][0] = packbf(s0[0], s0[1]);
                ph[mt][1] = packbf(s0[2], s0[3]);
                ph[mt][2] = packbf(s1[0], s1[1]);
                ph[mt][3] = packbf(s1[2], s1[3]);
                pl[mt][0] = packbf_lo(s0[0], s0[1], ph[mt][0]);
                pl[mt][1] = packbf_lo(s0[2], s0[3], ph[mt][1]);
                pl[mt][2] = packbf_lo(s1[0], s1[1], ph[mt][2]);
                pl[mt][3] = packbf_lo(s1[2], s1[3], ph[mt][3]);
            }
            #pragma unroll
            for (int np = 0; np < 4; ++np) {
                uint32_t vh[4], vl[4];
                int row = kt * 16 + vR;
                uint32_t off = (uint32_t)(row * 128)
                             + (uint32_t)((((np * 2 + vC) ^ (row & 7)) << 4));
                ldm_x4_t(vh, vb + off);
                ldm_x4_t(vl, vb + 8192 + off);
                #pragma unroll
                for (int mt = 0; mt < 2; ++mt) {
                    #pragma unroll
                    for (int d2 = 0; d2 < 2; ++d2) {
                        float* c = oacc[mt * 8 + np * 2 + d2];
                        mma16816(c, ph[mt], vh[d2*2], vh[d2*2+1]);
                        mma16816(c, ph[mt], vl[d2*2], vl[d2*2+1]);
                        mma16816(c, pl[mt], vh[d2*2], vh[d2*2+1]);
                    }
                }
            }
        }
    }

    // ---- finalize: 1/l, Gram-Schmidt exclusion, bf16 hi/lo store [b,s,d] ----
    #pragma unroll
    for (int mt = 0; mt < 2; ++mt) {
        float inv0 = 1.0f / lsum[mt][0];
        float inv1 = 1.0f / lsum[mt][1];
        #pragma unroll
        for (int t = 0; t < 8; ++t) {
            float* o = oacc[mt * 8 + t];
            o[0] *= inv0; o[1] *= inv0;
            o[2] *= inv1; o[3] *= inv1;
        }
    }

    const int bb = g >> 4, hh = g & 15;
    #pragma unroll
    for (int mt = 0; mt < 2; ++mt) {
        #pragma unroll
        for (int half = 0; half < 2; ++half) {
            int grow = m0 + wm + mt * 16 + (l >> 2) + half * 8;
            const float* vr = VF + gbase + (long)grow * HD_;
            float vv[16];
            float dov = 0.0f, dvv = 0.0f;
            #pragma unroll
            for (int nt = 0; nt < 8; ++nt) {
                float2 t = *(const float2*)(vr + nt * 8 + (l & 3) * 2);
                vv[2*nt] = t.x; vv[2*nt+1] = t.y;
                float o0 = oacc[mt * 8 + nt][half*2];
                float o1 = oacc[mt * 8 + nt][half*2+1];
                dov += o0 * t.x + o1 * t.y;
                dvv += t.x * t.x + t.y * t.y;
            }
            dov += __shfl_xor_sync(0xffffffffu, dov, 1);
            dov += __shfl_xor_sync(0xffffffffu, dov, 2);
            dvv += __shfl_xor_sync(0xffffffffu, dvv, 1);
            dvv += __shfl_xor_sync(0xffffffffu, dvv, 2);
            float al_ = dov / (dvv + 1e-8f);
            long obase = (long)(bb * S_ + grow) * D_ + hh * HD_;
            #pragma unroll
            for (int nt = 0; nt < 8; ++nt) {
                float rx = oacc[mt * 8 + nt][half*2]   - al_ * vv[2*nt];
                float ry = oacc[mt * 8 + nt][half*2+1] - al_ * vv[2*nt+1];
                long a = obase + nt * 8 + (l & 3) * 2;
                uint32_t hv = packbf(rx, ry);
                *(uint32_t*)(OBh + a) = hv;
                *(uint32_t*)(OBl + a) = packbf_lo(rx, ry, hv);
            }
        }
    }
}

// ============================================================================
extern "C" void kernel_launch(void* const* d_in, const int* in_sizes, int n_in,
                              void* d_out, int out_size)
{
    const float* x  = (const float*)d_in[0];
    const float* wq = (const float*)d_in[1];
    const float* bq = (const float*)d_in[2];
    const float* wk = (const float*)d_in[3];
    const float* bk = (const float*)d_in[4];
    const float* wv = (const float*)d_in[5];
    const float* bv = (const float*)d_in[6];
    const float* wo = (const float*)d_in[7];
    const float* bo = (const float*)d_in[8];
    float* out = (float*)d_out;

    __nv_bfloat16 *xh, *xl, *wh, *wl, *qh, *ql, *kh, *kl, *vh, *vl, *obh, *obl;
    float *vf;
    cudaGetSymbolAddress((void**)&xh,  g_xh);
    cudaGetSymbolAddress((void**)&xl,  g_xl);
    cudaGetSymbolAddress((void**)&wh,  g_wh);
    cudaGetSymbolAddress((void**)&wl,  g_wl);
    cudaGetSymbolAddress((void**)&qh,  g_qh);
    cudaGetSymbolAddress((void**)&ql,  g_ql);
    cudaGetSymbolAddress((void**)&kh,  g_kh);
    cudaGetSymbolAddress((void**)&kl,  g_kl);
    cudaGetSymbolAddress((void**)&vh,  g_vh);
    cudaGetSymbolAddress((void**)&vl,  g_vl);
    cudaGetSymbolAddress((void**)&vf,  g_vf);
    cudaGetSymbolAddress((void**)&obh, g_obh);
    cudaGetSymbolAddress((void**)&obl, g_obl);

    const int SMG = 4 * 49152;     // 196608
    const int SMF = 131072;        // Q 64K + K 32K + V 32K
    cudaFuncSetAttribute(gemm_qkv,  cudaFuncAttributeMaxDynamicSharedMemorySize, SMG);
    cudaFuncSetAttribute(gemm_out,  cudaFuncAttributeMaxDynamicSharedMemorySize, SMG);
    cudaFuncSetAttribute(fused_attn, cudaFuncAttributeMaxDynamicSharedMemorySize, SMF);

    // 0) convert x + weights to bf16 hi/lo
    convert_all<<<dim3(512, 8), 256>>>(x, wq, wk, wv, wo, xh, xl, wh, wl);

    // 1) Q/K/V projections -> bf16 hi/lo head layout (+ V fp32)
    gemm_qkv<<<dim3(D_/256, M_/128, 3), 256, SMG>>>(
        xh, xl, wh, wl, bq, bk, bv, qh, ql, kh, kl, vh, vl, vf);

    // 2) fused attention + softmax + exclusion -> ob bf16 hi/lo [b,s,d]
    fused_attn<<<dim3(S_/256, G_), 256, SMF>>>(
        qh, ql, kh, kl, vh, vl, vf, obh, obl);

    // 3) output projection -> d_out
    gemm_out<<<dim3(D_/256, M_/128, 1), 256, SMG>>>(obh, obl, wh, wl, bo, out);
}

// round 11
// speedup vs baseline: 1.5169x; 1.5169x over previous
#include <cuda_runtime.h>
#include <cuda_bf16.h>
#include <cstdint>

#define B_   2
#define S_   2048
#define D_   1024
#define H_   16
#define HD_  64
#define M_   (B_*S_)     // 4096
#define G_   (B_*H_)     // 32
#define NE_  ((size_t)M_*D_)   // 4194304

// ---- scratch (static device arrays; no allocation allowed) ----
__device__ __nv_bfloat16 g_xh[NE_], g_xl[NE_];      // x bf16 hi/lo
__device__ __nv_bfloat16 g_wh[NE_], g_wl[NE_];      // wq|wk|wv|wo hi/lo
__device__ __nv_bfloat16 g_qh[NE_], g_ql[NE_];      // Q head layout [g,s,hd]
__device__ __nv_bfloat16 g_kh[NE_], g_kl[NE_];
__device__ __nv_bfloat16 g_vh[NE_], g_vl[NE_];
__device__ float         g_vf[NE_];                 // V fp32 (exclusion)
__device__ __nv_bfloat16 g_obh[NE_], g_obl[NE_];    // attn out [b,s,d]

// ============================================================================
// helpers
// ============================================================================
__device__ __forceinline__ uint32_t smem_u32(const void* p) {
    uint32_t a;
    asm("{ .reg .u64 t; cvta.to.shared.u64 t, %1; cvt.u32.u64 %0, t; }"
        : "=r"(a) : "l"(p));
    return a;
}
__device__ __forceinline__ void ldm_x4(uint32_t* r, uint32_t addr) {
    asm volatile("ldmatrix.sync.aligned.m8n8.x4.shared.b16 {%0,%1,%2,%3}, [%4];"
        : "=r"(r[0]), "=r"(r[1]), "=r"(r[2]), "=r"(r[3]) : "r"(addr));
}
__device__ __forceinline__ void ldm_x4_t(uint32_t* r, uint32_t addr) {
    asm volatile("ldmatrix.sync.aligned.m8n8.x4.trans.shared.b16 {%0,%1,%2,%3}, [%4];"
        : "=r"(r[0]), "=r"(r[1]), "=r"(r[2]), "=r"(r[3]) : "r"(addr));
}
__device__ __forceinline__ void mma16816(float* c, const uint32_t* a,
                                         uint32_t b0, uint32_t b1) {
    asm volatile(
        "mma.sync.aligned.m16n8k16.row.col.f32.bf16.bf16.f32 "
        "{%0,%1,%2,%3}, {%4,%5,%6,%7}, {%8,%9}, {%0,%1,%2,%3};"
        : "+f"(c[0]), "+f"(c[1]), "+f"(c[2]), "+f"(c[3])
        : "r"(a[0]), "r"(a[1]), "r"(a[2]), "r"(a[3]), "r"(b0), "r"(b1));
}
__device__ __forceinline__ uint32_t packbf(float x, float y) {
    __nv_bfloat162 t;
    t.x = __float2bfloat16_rn(x);
    t.y = __float2bfloat16_rn(y);
    return *(uint32_t*)&t;
}
__device__ __forceinline__ uint32_t packbf_lo(float x, float y, uint32_t hi) {
    __nv_bfloat162 h = *(__nv_bfloat162*)&hi;
    return packbf(x - __bfloat162float(h.x), y - __bfloat162float(h.y));
}
__device__ __forceinline__ float fexp2(float x) {
    float y;
    asm("ex2.approx.f32 %0, %1;" : "=f"(y) : "f"(x));
    return y;
}
__device__ __forceinline__ void cpa(uint32_t dst, const void* src) {
    asm volatile("cp.async.cg.shared.global [%0], [%1], 16;"
        :: "r"(dst), "l"(src) : "memory");
}
#define CP_COMMIT() asm volatile("cp.async.commit_group;" ::: "memory")
#define CP_WAIT(n)  asm volatile("cp.async.wait_group %0;" :: "n"(n) : "memory")

// 0.125 (1/sqrt(64)) * log2(e)  -> softmax run in log2 domain
#define SSCALE 0.18033688f

// ============================================================================
// Convert pass: x (4 quarters) + 4 weights -> bf16 hi/lo
// ============================================================================
__global__ void __launch_bounds__(256)
convert_all(const float* __restrict__ x,
            const float* __restrict__ wq, const float* __restrict__ wk,
            const float* __restrict__ wv, const float* __restrict__ wo,
            __nv_bfloat16* __restrict__ xh, __nv_bfloat16* __restrict__ xl,
            __nv_bfloat16* __restrict__ wh, __nv_bfloat16* __restrict__ wl)
{
    const int z = blockIdx.y;
    const float* src;
    __nv_bfloat16 *dh, *dl;
    if (z < 4) {
        src = x  + ((long)z << 20);
        dh  = xh + ((long)z << 20);
        dl  = xl + ((long)z << 20);
    } else {
        const float* ws = (z == 4) ? wq : (z == 5) ? wk : (z == 6) ? wv : wo;
        src = ws;
        dh  = wh + ((long)(z - 4) << 20);
        dl  = wl + ((long)(z - 4) << 20);
    }
    long i = ((long)blockIdx.x * 256 + threadIdx.x) * 8;
    float4 a = *(const float4*)(src + i);
    float4 b = *(const float4*)(src + i + 4);
    uint32_t h0 = packbf(a.x, a.y), h1 = packbf(a.z, a.w);
    uint32_t h2 = packbf(b.x, b.y), h3 = packbf(b.z, b.w);
    uint32_t l0 = packbf_lo(a.x, a.y, h0), l1 = packbf_lo(a.z, a.w, h1);
    uint32_t l2 = packbf_lo(b.x, b.y, h2), l3 = packbf_lo(b.z, b.w, h3);
    *(uint4*)(dh + i) = make_uint4(h0, h1, h2, h3);
    *(uint4*)(dl + i) = make_uint4(l0, l1, l2, l3);
}

// ============================================================================
// bf16 cp.async GEMM: C = A W^T (+bias). BM=BN=128, BK=32, 3-stage pipeline,
// ONE barrier per chunk. MMA emission in 3 passes (hh, hl, lh) across all 16
// accumulators -> RAW distance 16.
// ============================================================================
__device__ __forceinline__ void gemm_issue(
    const __nv_bfloat16* __restrict__ Ah, const __nv_bfloat16* __restrict__ Al,
    const __nv_bfloat16* __restrict__ Wh, const __nv_bfloat16* __restrict__ Wl,
    int m0, int n0, int s, uint32_t sb, int tid)
{
    const int kc = s * 32;
    const uint32_t stb = sb + (uint32_t)((s % 3) * 32768);
    #pragma unroll
    for (int it = 0; it < 8; ++it) {
        int idx  = tid + it * 256;
        int bsel = idx >> 9;
        int ci   = idx & 511;
        int row  = ci >> 2, ch = ci & 3;
        const __nv_bfloat16* src =
            (bsel == 0) ? Ah + (long)(m0 + row) * 1024 + kc + ch * 8 :
            (bsel == 1) ? Al + (long)(m0 + row) * 1024 + kc + ch * 8 :
            (bsel == 2) ? Wh + (long)(n0 + row) * 1024 + kc + ch * 8 :
                          Wl + (long)(n0 + row) * 1024 + kc + ch * 8;
        uint32_t dst = stb + (uint32_t)(bsel * 8192) + (uint32_t)(row * 64)
                     + (uint32_t)(((ch ^ ((row >> 1) & 3)) << 4));
        cpa(dst, src);
    }
}

template<int MODE>
__device__ __forceinline__ void gemm_async(
    const __nv_bfloat16* __restrict__ Ah, const __nv_bfloat16* __restrict__ Al,
    const __nv_bfloat16* __restrict__ Wh, const __nv_bfloat16* __restrict__ Wl,
    const float* __restrict__ bias,
    float* __restrict__ Cf,
    __nv_bfloat16* __restrict__ Oh, __nv_bfloat16* __restrict__ Ol,
    float* __restrict__ Of,
    char* smem)
{
    const int tid = threadIdx.x;
    const int wid = tid >> 5;
    const int l   = tid & 31;
    const int m0  = blockIdx.y * 128;
    const int n0  = blockIdx.x * 128;
    const int wm  = (wid / 4) * 64;
    const int wn  = (wid % 4) * 32;

    const int aRow = (l & 15);
    const int aCk  = (l >> 4);
    const int bRow = ((l >> 4) & 1) * 8 + (l & 7);
    const int bCk  = (l >> 3) & 1;

    float acc[4][4][4];
    #pragma unroll
    for (int a = 0; a < 4; ++a)
        #pragma unroll
        for (int b = 0; b < 4; ++b)
            #pragma unroll
            for (int c = 0; c < 4; ++c) acc[a][b][c] = 0.0f;

    const uint32_t sb = smem_u32(smem);

    gemm_issue(Ah, Al, Wh, Wl, m0, n0, 0, sb, tid); CP_COMMIT();
    gemm_issue(Ah, Al, Wh, Wl, m0, n0, 1, sb, tid); CP_COMMIT();

    for (int c = 0; c < 32; ++c) {
        if (c < 31) { CP_WAIT(1); } else { CP_WAIT(0); }
        __syncthreads();
        if (c + 2 < 32) {
            gemm_issue(Ah, Al, Wh, Wl, m0, n0, c + 2, sb, tid);
            CP_COMMIT();
        }

        const uint32_t ahi = sb + (uint32_t)((c % 3) * 32768);
        const uint32_t alo = ahi + 8192;
        const uint32_t bhi = ahi + 16384;
        const uint32_t blo = ahi + 24576;

        #pragma unroll
        for (int ks = 0; ks < 2; ++ks) {
            uint32_t ah[4][4], al[4][4], bh[2][4], bl[2][4];
            #pragma unroll
            for (int mt = 0; mt < 4; ++mt) {
                int row = wm + mt * 16 + aRow;
                uint32_t off = (uint32_t)(row * 64)
                             + (uint32_t)((((2*ks + aCk) ^ ((row >> 1) & 3)) << 4));
                ldm_x4(ah[mt], ahi + off);
                ldm_x4(al[mt], alo + off);
            }
            #pragma unroll
            for (int nb = 0; nb < 2; ++nb) {
                int row = wn + nb * 16 + bRow;
                uint32_t off = (uint32_t)(row * 64)
                             + (uint32_t)((((2*ks + bCk) ^ ((row >> 1) & 3)) << 4));
                ldm_x4(bh[nb], bhi + off);
                ldm_x4(bl[nb], blo + off);
            }
            // pass 1: ah x bh  (16 independent MMAs)
            #pragma unroll
            for (int mt = 0; mt < 4; ++mt)
                #pragma unroll
                for (int nt = 0; nt < 4; ++nt) {
                    const uint32_t* pb = &bh[nt >> 1][(nt & 1) * 2];
                    mma16816(acc[mt][nt], ah[mt], pb[0], pb[1]);
                }
            // pass 2: ah x bl
            #pragma unroll
            for (int mt = 0; mt < 4; ++mt)
                #pragma unroll
                for (int nt = 0; nt < 4; ++nt) {
                    const uint32_t* pb = &bl[nt >> 1][(nt & 1) * 2];
                    mma16816(acc[mt][nt], ah[mt], pb[0], pb[1]);
                }
            // pass 3: al x bh
            #pragma unroll
            for (int mt = 0; mt < 4; ++mt)
                #pragma unroll
                for (int nt = 0; nt < 4; ++nt) {
                    const uint32_t* pb = &bh[nt >> 1][(nt & 1) * 2];
                    mma16816(acc[mt][nt], al[mt], pb[0], pb[1]);
                }
        }
    }

    #pragma unroll
    for (int mt = 0; mt < 4; ++mt) {
        #pragma unroll
        for (int nt = 0; nt < 4; ++nt) {
            int n = n0 + wn + nt * 8 + (l & 3) * 2;
            float2 bb = *(const float2*)(bias + n);
            #pragma unroll
            for (int half = 0; half < 2; ++half) {
                int m = m0 + wm + mt * 16 + (l >> 2) + half * 8;
                float2 r;
                r.x = acc[mt][nt][half*2]   + bb.x;
                r.y = acc[mt][nt][half*2+1] + bb.y;
                if (MODE == 0) {
                    *(float2*)(Cf + (long)m * 1024 + n) = r;
                } else {
                    int b2 = m >> 11, s = m & 2047;
                    int h = n >> 6, hd = n & 63;
                    long addr = ((long)(b2 * H_ + h) * S_ + s) * HD_ + hd;
                    uint32_t hv = packbf(r.x, r.y);
                    *(uint32_t*)(Oh + addr) = hv;
                    *(uint32_t*)(Ol + addr) = packbf_lo(r.x, r.y, hv);
                    if (Of) *(float2*)(Of + addr) = r;
                }
            }
        }
    }
}

__global__ void __launch_bounds__(256, 2)
gemm_qkv(const __nv_bfloat16* __restrict__ xh, const __nv_bfloat16* __restrict__ xl,
         const __nv_bfloat16* __restrict__ wh, const __nv_bfloat16* __restrict__ wl,
         const float* __restrict__ bq, const float* __restrict__ bk,
         const float* __restrict__ bv,
         __nv_bfloat16* __restrict__ qh, __nv_bfloat16* __restrict__ ql,
         __nv_bfloat16* __restrict__ kh, __nv_bfloat16* __restrict__ kl,
         __nv_bfloat16* __restrict__ vh, __nv_bfloat16* __restrict__ vl,
         float* __restrict__ vf)
{
    extern __shared__ char smem[];
    const int z = blockIdx.z;
    const __nv_bfloat16* Wh = wh + ((long)z << 20);
    const __nv_bfloat16* Wl = wl + ((long)z << 20);
    const float* bias = (z == 0) ? bq : (z == 1) ? bk : bv;
    __nv_bfloat16* Oh = (z == 0) ? qh : (z == 1) ? kh : vh;
    __nv_bfloat16* Ol = (z == 0) ? ql : (z == 1) ? kl : vl;
    float* Of = (z == 2) ? vf : nullptr;
    gemm_async<1>(xh, xl, Wh, Wl, bias, nullptr, Oh, Ol, Of, smem);
}

__global__ void __launch_bounds__(256, 2)
gemm_out(const __nv_bfloat16* __restrict__ ah, const __nv_bfloat16* __restrict__ al,
         const __nv_bfloat16* __restrict__ wh, const __nv_bfloat16* __restrict__ wl,
         const float* __restrict__ bias, float* __restrict__ C)
{
    extern __shared__ char smem[];
    gemm_async<0>(ah, al, wh + ((long)3 << 20), wl + ((long)3 << 20),
                  bias, C, nullptr, nullptr, nullptr, smem);
}

// ============================================================================
// Fused attention, 2 CTAs/SM: KV block 64 rows, 32 iterations.
// smem: Q hi/lo 32K | K 2x16K | V 2x16K = 96 KB.
// MMA emission reordered into 3 passes per fragment pair (RAW distance 4).
// ============================================================================
__device__ __forceinline__ void issue_q(const __nv_bfloat16* __restrict__ Gh,
    const __nv_bfloat16* __restrict__ Gl, uint32_t dst_hi, int tid)
{
    #pragma unroll
    for (int it = 0; it < 4; ++it) {
        int idx = tid + it * 256;
        int row = idx >> 3, ch = idx & 7;
        uint32_t off = (uint32_t)(row * 128) + (uint32_t)(((ch ^ (row & 7)) << 4));
        cpa(dst_hi + off,         Gh + row * 64 + ch * 8);
        cpa(dst_hi + 16384 + off, Gl + row * 64 + ch * 8);
    }
}
__device__ __forceinline__ void issue_kv64(const __nv_bfloat16* __restrict__ Gh,
    const __nv_bfloat16* __restrict__ Gl, uint32_t dst_hi, int tid)
{
    #pragma unroll
    for (int it = 0; it < 2; ++it) {
        int idx = tid + it * 256;       // 0..511
        int row = idx >> 3, ch = idx & 7;
        uint32_t off = (uint32_t)(row * 128) + (uint32_t)(((ch ^ (row & 7)) << 4));
        cpa(dst_hi + off,        Gh + row * 64 + ch * 8);
        cpa(dst_hi + 8192 + off, Gl + row * 64 + ch * 8);
    }
}

__global__ void __launch_bounds__(256, 2)
fused_attn(const __nv_bfloat16* __restrict__ Qh, const __nv_bfloat16* __restrict__ Ql,
           const __nv_bfloat16* __restrict__ Kh, const __nv_bfloat16* __restrict__ Kl,
           const __nv_bfloat16* __restrict__ Vh, const __nv_bfloat16* __restrict__ Vl,
           const float* __restrict__ VF,
           __nv_bfloat16* __restrict__ OBh, __nv_bfloat16* __restrict__ OBl)
{
    extern __shared__ char sm[];
    const int tid = threadIdx.x;
    const int wid = tid >> 5;
    const int l   = tid & 31;
    const int g   = blockIdx.y;
    const int m0  = blockIdx.x * 128;
    const int wm  = wid * 16;

    const long gbase = (long)g * S_ * HD_;
    const __nv_bfloat16* Kgh = Kh + gbase;
    const __nv_bfloat16* Kgl = Kl + gbase;
    const __nv_bfloat16* Vgh = Vh + gbase;
    const __nv_bfloat16* Vgl = Vl + gbase;

    const uint32_t sb = smem_u32(sm);
    const uint32_t qb = sb;

    // prologue: Q + K0 + V0 as group 0
    issue_q(Qh + gbase + (long)m0 * HD_, Ql + gbase + (long)m0 * HD_, sb, tid);
    issue_kv64(Kgh, Kgl, sb + 32768, tid);
    issue_kv64(Vgh, Vgl, sb + 65536, tid);
    CP_COMMIT();

    float oacc[8][4];
    #pragma unroll
    for (int i = 0; i < 8; ++i)
        #pragma unroll
        for (int j = 0; j < 4; ++j) oacc[i][j] = 0.0f;
    float mrun[2] = {-1e30f, -1e30f};   // log2 domain
    float lsum[2] = {0.0f, 0.0f};

    const int aR = wm + (l & 15);
    const int bR = ((l >> 4) & 1) * 8 + (l & 7);
    const int bC = (l >> 3) & 1;
    const int vR = (l & 15);
    const int vC = (l >> 4);

    for (int j = 0; j < 32; ++j) {
        const int cur = j & 1;
        const uint32_t kb = sb + 32768 + cur * 16384;
        const uint32_t vb = sb + 65536 + cur * 16384;

        __syncthreads();   // buffer (j+1)&1 free (consumed in iter j-1)
        if (j + 1 < 32) {
            const int nxt = cur ^ 1;
            issue_kv64(Kgh + (long)(j + 1) * 4096, Kgl + (long)(j + 1) * 4096,
                       sb + 32768 + nxt * 16384, tid);
            issue_kv64(Vgh + (long)(j + 1) * 4096, Vgl + (long)(j + 1) * 4096,
                       sb + 65536 + nxt * 16384, tid);
            CP_COMMIT();
        }
        if (j < 31) { CP_WAIT(1); } else { CP_WAIT(0); }
        __syncthreads();

        // ---- S = Q K^T : warp tile 16 x 64 ----
        float sacc[8][4];
        #pragma unroll
        for (int i = 0; i < 8; ++i)
            #pragma unroll
            for (int c = 0; c < 4; ++c) sacc[i][c] = 0.0f;

        #pragma unroll
        for (int ks = 0; ks < 4; ++ks) {
            uint32_t ah[4], al[4];
            {
                uint32_t off = (uint32_t)(aR * 128)
                             + (uint32_t)((((ks * 2 + (l >> 4)) ^ (aR & 7)) << 4));
                ldm_x4(ah, qb + off);
                ldm_x4(al, qb + 16384 + off);
            }
            #pragma unroll
            for (int nbp = 0; nbp < 4; nbp += 2) {
                uint32_t bh[2][4], bl[2][4];
                #pragma unroll
                for (int i = 0; i < 2; ++i) {
                    int row = (nbp + i) * 16 + bR;
                    uint32_t off = (uint32_t)(row * 128)
                                 + (uint32_t)((((ks * 2 + bC) ^ (row & 7)) << 4));
                    ldm_x4(bh[i], kb + off);
                    ldm_x4(bl[i], kb + 8192 + off);
                }
                // pass 1: ah x bh (4 independent)
                #pragma unroll
                for (int i = 0; i < 2; ++i)
                    #pragma unroll
                    for (int nt2 = 0; nt2 < 2; ++nt2)
                        mma16816(sacc[(nbp + i) * 2 + nt2], ah,
                                 bh[i][nt2*2], bh[i][nt2*2+1]);
                // pass 2: ah x bl
                #pragma unroll
                for (int i = 0; i < 2; ++i)
                    #pragma unroll
                    for (int nt2 = 0; nt2 < 2; ++nt2)
                        mma16816(sacc[(nbp + i) * 2 + nt2], ah,
                                 bl[i][nt2*2], bl[i][nt2*2+1]);
                // pass 3: al x bh
                #pragma unroll
                for (int i = 0; i < 2; ++i)
                    #pragma unroll
                    for (int nt2 = 0; nt2 < 2; ++nt2)
                        mma16816(sacc[(nbp + i) * 2 + nt2], al,
                                 bh[i][nt2*2], bh[i][nt2*2+1]);
            }
        }

        // ---- online softmax (log2 domain; rows h=0 -> l>>2, h=1 -> +8) ----
        float mnew[2] = {-1e30f, -1e30f};
        #pragma unroll
        for (int nt = 0; nt < 8; ++nt) {
            #pragma unroll
            for (int c = 0; c < 4; ++c) sacc[nt][c] *= SSCALE;
            mnew[0] = fmaxf(mnew[0], fmaxf(sacc[nt][0], sacc[nt][1]));
            mnew[1] = fmaxf(mnew[1], fmaxf(sacc[nt][2], sacc[nt][3]));
        }
        #pragma unroll
        for (int h = 0; h < 2; ++h) {
            mnew[h] = fmaxf(mnew[h], __shfl_xor_sync(0xffffffffu, mnew[h], 1));
            mnew[h] = fmaxf(mnew[h], __shfl_xor_sync(0xffffffffu, mnew[h], 2));
        }
        float corr[2];
        #pragma unroll
        for (int h = 0; h < 2; ++h) {
            float mi = fmaxf(mrun[h], mnew[h]);
            corr[h] = fexp2(mrun[h] - mi);
            mrun[h] = mi;
            lsum[h] *= corr[h];
        }
        float rs[2] = {0.0f, 0.0f};
        #pragma unroll
        for (int nt = 0; nt < 8; ++nt) {
            sacc[nt][0] = fexp2(sacc[nt][0] - mrun[0]);
            sacc[nt][1] = fexp2(sacc[nt][1] - mrun[0]);
            sacc[nt][2] = fexp2(sacc[nt][2] - mrun[1]);
            sacc[nt][3] = fexp2(sacc[nt][3] - mrun[1]);
            rs[0] += sacc[nt][0] + sacc[nt][1];
            rs[1] += sacc[nt][2] + sacc[nt][3];
        }
        #pragma unroll
        for (int h = 0; h < 2; ++h) {
            rs[h] += __shfl_xor_sync(0xffffffffu, rs[h], 1);
            rs[h] += __shfl_xor_sync(0xffffffffu, rs[h], 2);
            lsum[h] += rs[h];
        }
        #pragma unroll
        for (int nt = 0; nt < 8; ++nt) {
            oacc[nt][0] *= corr[0]; oacc[nt][1] *= corr[0];
            oacc[nt][2] *= corr[1]; oacc[nt][3] *= corr[1];
        }

        // ---- O += P V (np pairs, 3-pass reorder) ----
        #pragma unroll
        for (int kt = 0; kt < 4; ++kt) {
            uint32_t ph[4], pl[4];
            ph[0] = packbf(sacc[2*kt][0],   sacc[2*kt][1]);
            ph[1] = packbf(sacc[2*kt][2],   sacc[2*kt][3]);
            ph[2] = packbf(sacc[2*kt+1][0], sacc[2*kt+1][1]);
            ph[3] = packbf(sacc[2*kt+1][2], sacc[2*kt+1][3]);
            pl[0] = packbf_lo(sacc[2*kt][0],   sacc[2*kt][1],   ph[0]);
            pl[1] = packbf_lo(sacc[2*kt][2],   sacc[2*kt][3],   ph[1]);
            pl[2] = packbf_lo(sacc[2*kt+1][0], sacc[2*kt+1][1], ph[2]);
            pl[3] = packbf_lo(sacc[2*kt+1][2], sacc[2*kt+1][3], ph[3]);
            #pragma unroll
            for (int npp = 0; npp < 4; npp += 2) {
                uint32_t vh[2][4], vl[2][4];
                #pragma unroll
                for (int i = 0; i < 2; ++i) {
                    int row = kt * 16 + vR;
                    uint32_t off = (uint32_t)(row * 128)
                                 + (uint32_t)(((((npp + i) * 2 + vC) ^ (row & 7)) << 4));
                    ldm_x4_t(vh[i], vb + off);
                    ldm_x4_t(vl[i], vb + 8192 + off);
                }
                // pass 1: ph x vh
                #pragma unroll
                for (int i = 0; i < 2; ++i)
                    #pragma unroll
                    for (int d2 = 0; d2 < 2; ++d2)
                        mma16816(oacc[(npp + i) * 2 + d2], ph,
                                 vh[i][d2*2], vh[i][d2*2+1]);
                // pass 2: ph x vl
                #pragma unroll
                for (int i = 0; i < 2; ++i)
                    #pragma unroll
                    for (int d2 = 0; d2 < 2; ++d2)
                        mma16816(oacc[(npp + i) * 2 + d2], ph,
                                 vl[i][d2*2], vl[i][d2*2+1]);
                // pass 3: pl x vh
                #pragma unroll
                for (int i = 0; i < 2; ++i)
                    #pragma unroll
                    for (int d2 = 0; d2 < 2; ++d2)
                        mma16816(oacc[(npp + i) * 2 + d2], pl,
                                 vh[i][d2*2], vh[i][d2*2+1]);
            }
        }
    }

    // ---- finalize: 1/l, Gram-Schmidt exclusion, bf16 hi/lo store [b,s,d] ----
    float inv[2] = {1.0f / lsum[0], 1.0f / lsum[1]};
    #pragma unroll
    for (int nt = 0; nt < 8; ++nt) {
        oacc[nt][0] *= inv[0]; oacc[nt][1] *= inv[0];
        oacc[nt][2] *= inv[1]; oacc[nt][3] *= inv[1];
    }

    const int bb = g >> 4, hh = g & 15;
    #pragma unroll
    for (int half = 0; half < 2; ++half) {
        int grow = m0 + wm + (l >> 2) + half * 8;
        const float* vr = VF + gbase + (long)grow * HD_;
        float vv[16];
        float dov = 0.0f, dvv = 0.0f;
        #pragma unroll
        for (int nt = 0; nt < 8; ++nt) {
            float2 t = *(const float2*)(vr + nt * 8 + (l & 3) * 2);
            vv[2*nt] = t.x; vv[2*nt+1] = t.y;
            float o0 = oacc[nt][half*2], o1 = oacc[nt][half*2+1];
            dov += o0 * t.x + o1 * t.y;
            dvv += t.x * t.x + t.y * t.y;
        }
        dov += __shfl_xor_sync(0xffffffffu, dov, 1);
        dov += __shfl_xor_sync(0xffffffffu, dov, 2);
        dvv += __shfl_xor_sync(0xffffffffu, dvv, 1);
        dvv += __shfl_xor_sync(0xffffffffu, dvv, 2);
        float al_ = dov / (dvv + 1e-8f);
        long obase = (long)(bb * S_ + grow) * D_ + hh * HD_;
        #pragma unroll
        for (int nt = 0; nt < 8; ++nt) {
            float rx = oacc[nt][half*2]   - al_ * vv[2*nt];
            float ry = oacc[nt][half*2+1] - al_ * vv[2*nt+1];
            long a = obase + nt * 8 + (l & 3) * 2;
            uint32_t hv = packbf(rx, ry);
            *(uint32_t*)(OBh + a) = hv;
            *(uint32_t*)(OBl + a) = packbf_lo(rx, ry, hv);
        }
    }
}

// ============================================================================
extern "C" void kernel_launch(void* const* d_in, const int* in_sizes, int n_in,
                              void* d_out, int out_size)
{
    const float* x  = (const float*)d_in[0];
    const float* wq = (const float*)d_in[1];
    const float* bq = (const float*)d_in[2];
    const float* wk = (const float*)d_in[3];
    const float* bk = (const float*)d_in[4];
    const float* wv = (const float*)d_in[5];
    const float* bv = (const float*)d_in[6];
    const float* wo = (const float*)d_in[7];
    const float* bo = (const float*)d_in[8];
    float* out = (float*)d_out;

    __nv_bfloat16 *xh, *xl, *wh, *wl, *qh, *ql, *kh, *kl, *vh, *vl, *obh, *obl;
    float *vf;
    cudaGetSymbolAddress((void**)&xh,  g_xh);
    cudaGetSymbolAddress((void**)&xl,  g_xl);
    cudaGetSymbolAddress((void**)&wh,  g_wh);
    cudaGetSymbolAddress((void**)&wl,  g_wl);
    cudaGetSymbolAddress((void**)&qh,  g_qh);
    cudaGetSymbolAddress((void**)&ql,  g_ql);
    cudaGetSymbolAddress((void**)&kh,  g_kh);
    cudaGetSymbolAddress((void**)&kl,  g_kl);
    cudaGetSymbolAddress((void**)&vh,  g_vh);
    cudaGetSymbolAddress((void**)&vl,  g_vl);
    cudaGetSymbolAddress((void**)&vf,  g_vf);
    cudaGetSymbolAddress((void**)&obh, g_obh);
    cudaGetSymbolAddress((void**)&obl, g_obl);

    const int SMG = 3 * 32768;     // 98304
    const int SMF = 98304;         // Q 32K + K 32K + V 32K
    cudaFuncSetAttribute(gemm_qkv,  cudaFuncAttributeMaxDynamicSharedMemorySize, SMG);
    cudaFuncSetAttribute(gemm_out,  cudaFuncAttributeMaxDynamicSharedMemorySize, SMG);
    cudaFuncSetAttribute(fused_attn, cudaFuncAttributeMaxDynamicSharedMemorySize, SMF);

    // 0) convert x + weights to bf16 hi/lo
    convert_all<<<dim3(512, 8), 256>>>(x, wq, wk, wv, wo, xh, xl, wh, wl);

    // 1) Q/K/V projections -> bf16 hi/lo head layout (+ V fp32)
    gemm_qkv<<<dim3(D_/128, M_/128, 3), 256, SMG>>>(
        xh, xl, wh, wl, bq, bk, bv, qh, ql, kh, kl, vh, vl, vf);

    // 2) fused attention + softmax + exclusion -> ob bf16 hi/lo [b,s,d]
    fused_attn<<<dim3(S_/128, G_), 256, SMF>>>(
        qh, ql, kh, kl, vh, vl, vf, obh, obl);

    // 3) output projection -> d_out
    gemm_out<<<dim3(D_/128, M_/128, 1), 256, SMG>>>(obh, obl, wh, wl, bo, out);
}

// round 12
// speedup vs baseline: 1.7263x; 1.1381x over previous
#include <cuda_runtime.h>
#include <cuda_fp16.h>
#include <cstdint>

#define B_   2
#define S_   2048
#define D_   1024
#define H_   16
#define HD_  64
#define M_   (B_*S_)     // 4096
#define G_   (B_*H_)     // 32
#define NE_  ((size_t)M_*D_)   // 4194304

// ---- scratch (static device arrays; no allocation allowed) ----
__device__ __half g_xh[NE_], g_xl[NE_];      // x fp16 hi/lo
__device__ __half g_wh[NE_], g_wl[NE_];      // wq|wk|wv|wo hi/lo
__device__ __half g_qh[NE_], g_ql[NE_];      // Q head layout [g,s,hd]
__device__ __half g_kh[NE_], g_kl[NE_];
__device__ __half g_vh[NE_];                 // V fp16 (single plane)
__device__ float  g_vf[NE_];                 // V fp32 (exclusion)
__device__ __half g_obh[NE_], g_obl[NE_];    // attn out [b,s,d]

// ============================================================================
// helpers
// ============================================================================
__device__ __forceinline__ uint32_t smem_u32(const void* p) {
    uint32_t a;
    asm("{ .reg .u64 t; cvta.to.shared.u64 t, %1; cvt.u32.u64 %0, t; }"
        : "=r"(a) : "l"(p));
    return a;
}
__device__ __forceinline__ void ldm_x4(uint32_t* r, uint32_t addr) {
    asm volatile("ldmatrix.sync.aligned.m8n8.x4.shared.b16 {%0,%1,%2,%3}, [%4];"
        : "=r"(r[0]), "=r"(r[1]), "=r"(r[2]), "=r"(r[3]) : "r"(addr));
}
__device__ __forceinline__ void ldm_x4_t(uint32_t* r, uint32_t addr) {
    asm volatile("ldmatrix.sync.aligned.m8n8.x4.trans.shared.b16 {%0,%1,%2,%3}, [%4];"
        : "=r"(r[0]), "=r"(r[1]), "=r"(r[2]), "=r"(r[3]) : "r"(addr));
}
__device__ __forceinline__ void mma16816(float* c, const uint32_t* a,
                                         uint32_t b0, uint32_t b1) {
    asm volatile(
        "mma.sync.aligned.m16n8k16.row.col.f32.f16.f16.f32 "
        "{%0,%1,%2,%3}, {%4,%5,%6,%7}, {%8,%9}, {%0,%1,%2,%3};"
        : "+f"(c[0]), "+f"(c[1]), "+f"(c[2]), "+f"(c[3])
        : "r"(a[0]), "r"(a[1]), "r"(a[2]), "r"(a[3]), "r"(b0), "r"(b1));
}
__device__ __forceinline__ uint32_t packh(float x, float y) {
    __half2 t = __floats2half2_rn(x, y);
    return *(uint32_t*)&t;
}
__device__ __forceinline__ uint32_t packh_lo(float x, float y, uint32_t hi) {
    __half2 h = *(__half2*)&hi;
    return packh(x - __half2float(h.x), y - __half2float(h.y));
}
__device__ __forceinline__ float fexp2(float x) {
    float y;
    asm("ex2.approx.f32 %0, %1;" : "=f"(y) : "f"(x));
    return y;
}
__device__ __forceinline__ void cpa(uint32_t dst, const void* src) {
    asm volatile("cp.async.cg.shared.global [%0], [%1], 16;"
        :: "r"(dst), "l"(src) : "memory");
}
#define CP_COMMIT() asm volatile("cp.async.commit_group;" ::: "memory")
#define CP_WAIT(n)  asm volatile("cp.async.wait_group %0;" :: "n"(n) : "memory")

// 0.125 (1/sqrt(64)) * log2(e)  -> softmax run in log2 domain
#define SSCALE 0.18033688f

// ============================================================================
// Convert pass: x (4 quarters) + 4 weights -> fp16 hi/lo
// ============================================================================
__global__ void __launch_bounds__(256)
convert_all(const float* __restrict__ x,
            const float* __restrict__ wq, const float* __restrict__ wk,
            const float* __restrict__ wv, const float* __restrict__ wo,
            __half* __restrict__ xh, __half* __restrict__ xl,
            __half* __restrict__ wh, __half* __restrict__ wl)
{
    const int z = blockIdx.y;
    const float* src;
    __half *dh, *dl;
    if (z < 4) {
        src = x  + ((long)z << 20);
        dh  = xh + ((long)z << 20);
        dl  = xl + ((long)z << 20);
    } else {
        const float* ws = (z == 4) ? wq : (z == 5) ? wk : (z == 6) ? wv : wo;
        src = ws;
        dh  = wh + ((long)(z - 4) << 20);
        dl  = wl + ((long)(z - 4) << 20);
    }
    long i = ((long)blockIdx.x * 256 + threadIdx.x) * 8;
    float4 a = *(const float4*)(src + i);
    float4 b = *(const float4*)(src + i + 4);
    uint32_t h0 = packh(a.x, a.y), h1 = packh(a.z, a.w);
    uint32_t h2 = packh(b.x, b.y), h3 = packh(b.z, b.w);
    uint32_t l0 = packh_lo(a.x, a.y, h0), l1 = packh_lo(a.z, a.w, h1);
    uint32_t l2 = packh_lo(b.x, b.y, h2), l3 = packh_lo(b.z, b.w, h3);
    *(uint4*)(dh + i) = make_uint4(h0, h1, h2, h3);
    *(uint4*)(dl + i) = make_uint4(l0, l1, l2, l3);
}

// ============================================================================
// fp16 cp.async GEMM: C = A W^T (+bias). BM=BN=128, BK=32, 3-stage pipeline.
// BS=1: B split hi/lo, 3-MMA (hh, hl, lh). Stage 32KB.
// BS=0: B single,      2-MMA (hh, lh).     Stage 24KB.
// ============================================================================
template<int BS>
__device__ __forceinline__ void gemm_issue(
    const __half* __restrict__ Ah, const __half* __restrict__ Al,
    const __half* __restrict__ Wh, const __half* __restrict__ Wl,
    int m0, int n0, int s, uint32_t sb, int tid)
{
    const int kc = s * 32;
    const uint32_t STGB = BS ? 32768u : 24576u;
    const uint32_t stb = sb + (uint32_t)(s % 3) * STGB;
    constexpr int ITERS = BS ? 8 : 6;
    #pragma unroll
    for (int it = 0; it < ITERS; ++it) {
        int idx  = tid + it * 256;
        int bsel = idx >> 9;                 // 0=Ah 1=Al 2=Wh (3=Wl if BS)
        int ci   = idx & 511;
        int row  = ci >> 2, ch = ci & 3;
        const __half* src =
            (bsel == 0) ? Ah + (long)(m0 + row) * 1024 + kc + ch * 8 :
            (bsel == 1) ? Al + (long)(m0 + row) * 1024 + kc + ch * 8 :
            (bsel == 2) ? Wh + (long)(n0 + row) * 1024 + kc + ch * 8 :
                          Wl + (long)(n0 + row) * 1024 + kc + ch * 8;
        uint32_t dst = stb + (uint32_t)(bsel * 8192) + (uint32_t)(row * 64)
                     + (uint32_t)(((ch ^ ((row >> 1) & 3)) << 4));
        cpa(dst, src);
    }
}

template<int MODE, int BS>
__device__ __forceinline__ void gemm_async(
    const __half* __restrict__ Ah, const __half* __restrict__ Al,
    const __half* __restrict__ Wh, const __half* __restrict__ Wl,
    const float* __restrict__ bias,
    float* __restrict__ Cf,
    __half* __restrict__ Oh, __half* __restrict__ Ol,
    float* __restrict__ Of,
    char* smem)
{
    const int tid = threadIdx.x;
    const int wid = tid >> 5;
    const int l   = tid & 31;
    const int m0  = blockIdx.y * 128;
    const int n0  = blockIdx.x * 128;
    const int wm  = (wid / 4) * 64;
    const int wn  = (wid % 4) * 32;

    const int aRow = (l & 15);
    const int aCk  = (l >> 4);
    const int bRow = ((l >> 4) & 1) * 8 + (l & 7);
    const int bCk  = (l >> 3) & 1;
    const uint32_t STGB = BS ? 32768u : 24576u;

    float acc[4][4][4];
    #pragma unroll
    for (int a = 0; a < 4; ++a)
        #pragma unroll
        for (int b = 0; b < 4; ++b)
            #pragma unroll
            for (int c = 0; c < 4; ++c) acc[a][b][c] = 0.0f;

    const uint32_t sb = smem_u32(smem);

    gemm_issue<BS>(Ah, Al, Wh, Wl, m0, n0, 0, sb, tid); CP_COMMIT();
    gemm_issue<BS>(Ah, Al, Wh, Wl, m0, n0, 1, sb, tid); CP_COMMIT();

    for (int c = 0; c < 32; ++c) {
        if (c < 31) { CP_WAIT(1); } else { CP_WAIT(0); }
        __syncthreads();
        if (c + 2 < 32) {
            gemm_issue<BS>(Ah, Al, Wh, Wl, m0, n0, c + 2, sb, tid);
            CP_COMMIT();
        }

        const uint32_t stb = sb + (uint32_t)(c % 3) * STGB;
        const uint32_t ahi = stb;
        const uint32_t alo = stb + 8192;
        const uint32_t bhi = stb + 16384;
        const uint32_t blo = stb + 24576;    // only valid when BS=1

        #pragma unroll
        for (int ks = 0; ks < 2; ++ks) {
            uint32_t ah[4][4], al[4][4], bh[2][4], bl[2][4];
            #pragma unroll
            for (int mt = 0; mt < 4; ++mt) {
                int row = wm + mt * 16 + aRow;
                uint32_t off = (uint32_t)(row * 64)
                             + (uint32_t)((((2*ks + aCk) ^ ((row >> 1) & 3)) << 4));
                ldm_x4(ah[mt], ahi + off);
                ldm_x4(al[mt], alo + off);
            }
            #pragma unroll
            for (int nb = 0; nb < 2; ++nb) {
                int row = wn + nb * 16 + bRow;
                uint32_t off = (uint32_t)(row * 64)
                             + (uint32_t)((((2*ks + bCk) ^ ((row >> 1) & 3)) << 4));
                ldm_x4(bh[nb], bhi + off);
                if (BS) ldm_x4(bl[nb], blo + off);
            }
            // pass 1: ah x bh
            #pragma unroll
            for (int mt = 0; mt < 4; ++mt)
                #pragma unroll
                for (int nt = 0; nt < 4; ++nt) {
                    const uint32_t* pb = &bh[nt >> 1][(nt & 1) * 2];
                    mma16816(acc[mt][nt], ah[mt], pb[0], pb[1]);
                }
            // pass 2 (BS only): ah x bl
            if (BS) {
                #pragma unroll
                for (int mt = 0; mt < 4; ++mt)
                    #pragma unroll
                    for (int nt = 0; nt < 4; ++nt) {
                        const uint32_t* pb = &bl[nt >> 1][(nt & 1) * 2];
                        mma16816(acc[mt][nt], ah[mt], pb[0], pb[1]);
                    }
            }
            // pass 3: al x bh
            #pragma unroll
            for (int mt = 0; mt < 4; ++mt)
                #pragma unroll
                for (int nt = 0; nt < 4; ++nt) {
                    const uint32_t* pb = &bh[nt >> 1][(nt & 1) * 2];
                    mma16816(acc[mt][nt], al[mt], pb[0], pb[1]);
                }
        }
    }

    #pragma unroll
    for (int mt = 0; mt < 4; ++mt) {
        #pragma unroll
        for (int nt = 0; nt < 4; ++nt) {
            int n = n0 + wn + nt * 8 + (l & 3) * 2;
            float2 bb = *(const float2*)(bias + n);
            #pragma unroll
            for (int half = 0; half < 2; ++half) {
                int m = m0 + wm + mt * 16 + (l >> 2) + half * 8;
                float2 r;
                r.x = acc[mt][nt][half*2]   + bb.x;
                r.y = acc[mt][nt][half*2+1] + bb.y;
                if (MODE == 0) {
                    *(float2*)(Cf + (long)m * 1024 + n) = r;
                } else {
                    int b2 = m >> 11, s = m & 2047;
                    int h = n >> 6, hd = n & 63;
                    long addr = ((long)(b2 * H_ + h) * S_ + s) * HD_ + hd;
                    uint32_t hv = packh(r.x, r.y);
                    *(uint32_t*)(Oh + addr) = hv;
                    if (Ol) *(uint32_t*)(Ol + addr) = packh_lo(r.x, r.y, hv);
                    if (Of) *(float2*)(Of + addr) = r;
                }
            }
        }
    }
}

__global__ void __launch_bounds__(256, 2)
gemm_qkv(const __half* __restrict__ xh, const __half* __restrict__ xl,
         const __half* __restrict__ wh, const __half* __restrict__ wl,
         const float* __restrict__ bq, const float* __restrict__ bk,
         const float* __restrict__ bv,
         __half* __restrict__ qh, __half* __restrict__ ql,
         __half* __restrict__ kh, __half* __restrict__ kl,
         __half* __restrict__ vh, float* __restrict__ vf)
{
    extern __shared__ char smem[];
    const int z = blockIdx.z;
    const __half* Wh = wh + ((long)z << 20);
    const __half* Wl = wl + ((long)z << 20);
    const float* bias = (z == 0) ? bq : (z == 1) ? bk : bv;
    __half* Oh = (z == 0) ? qh : (z == 1) ? kh : vh;
    __half* Ol = (z == 0) ? ql : (z == 1) ? kl : nullptr;
    float* Of = (z == 2) ? vf : nullptr;
    gemm_async<1, 1>(xh, xl, Wh, Wl, bias, nullptr, Oh, Ol, Of, smem);
}

__global__ void __launch_bounds__(256, 2)
gemm_out(const __half* __restrict__ ah, const __half* __restrict__ al,
         const __half* __restrict__ wh,
         const float* __restrict__ bias, float* __restrict__ C)
{
    extern __shared__ char smem[];
    gemm_async<0, 0>(ah, al, wh + ((long)3 << 20), nullptr,
                     bias, C, nullptr, nullptr, nullptr, smem);
}

// ============================================================================
// Fused attention, 2 CTAs/SM: KV block 64 rows, 32 iterations.
// smem: Q hi/lo 32K | K 2x16K (hi+lo) | V 2x8K (single) = 80 KB.
// QK^T: 3-MMA (K split). PV: 2-MMA (P split, V single).
// ============================================================================
__device__ __forceinline__ void issue_q(const __half* __restrict__ Gh,
    const __half* __restrict__ Gl, uint32_t dst_hi, int tid)
{
    #pragma unroll
    for (int it = 0; it < 4; ++it) {
        int idx = tid + it * 256;
        int row = idx >> 3, ch = idx & 7;
        uint32_t off = (uint32_t)(row * 128) + (uint32_t)(((ch ^ (row & 7)) << 4));
        cpa(dst_hi + off,         Gh + row * 64 + ch * 8);
        cpa(dst_hi + 16384 + off, Gl + row * 64 + ch * 8);
    }
}
__device__ __forceinline__ void issue_k64(const __half* __restrict__ Gh,
    const __half* __restrict__ Gl, uint32_t dst_hi, int tid)
{
    #pragma unroll
    for (int it = 0; it < 2; ++it) {
        int idx = tid + it * 256;       // 0..511
        int row = idx >> 3, ch = idx & 7;
        uint32_t off = (uint32_t)(row * 128) + (uint32_t)(((ch ^ (row & 7)) << 4));
        cpa(dst_hi + off,        Gh + row * 64 + ch * 8);
        cpa(dst_hi + 8192 + off, Gl + row * 64 + ch * 8);
    }
}
__device__ __forceinline__ void issue_v64(const __half* __restrict__ Gh,
    uint32_t dst, int tid)
{
    #pragma unroll
    for (int it = 0; it < 2; ++it) {
        int idx = tid + it * 256;       // 0..511
        int row = idx >> 3, ch = idx & 7;
        uint32_t off = (uint32_t)(row * 128) + (uint32_t)(((ch ^ (row & 7)) << 4));
        cpa(dst + off, Gh + row * 64 + ch * 8);
    }
}

__global__ void __launch_bounds__(256, 2)
fused_attn(const __half* __restrict__ Qh, const __half* __restrict__ Ql,
           const __half* __restrict__ Kh, const __half* __restrict__ Kl,
           const __half* __restrict__ Vh, const float* __restrict__ VF,
           __half* __restrict__ OBh, __half* __restrict__ OBl)
{
    extern __shared__ char sm[];
    const int tid = threadIdx.x;
    const int wid = tid >> 5;
    const int l   = tid & 31;
    const int g   = blockIdx.y;
    const int m0  = blockIdx.x * 128;
    const int wm  = wid * 16;

    const long gbase = (long)g * S_ * HD_;
    const __half* Kgh = Kh + gbase;
    const __half* Kgl = Kl + gbase;
    const __half* Vgh = Vh + gbase;

    const uint32_t sb = smem_u32(sm);
    const uint32_t qb = sb;

    // prologue: Q + K0 + V0 as group 0
    issue_q(Qh + gbase + (long)m0 * HD_, Ql + gbase + (long)m0 * HD_, sb, tid);
    issue_k64(Kgh, Kgl, sb + 32768, tid);
    issue_v64(Vgh, sb + 65536, tid);
    CP_COMMIT();

    float oacc[8][4];
    #pragma unroll
    for (int i = 0; i < 8; ++i)
        #pragma unroll
        for (int j = 0; j < 4; ++j) oacc[i][j] = 0.0f;
    float mrun[2] = {-1e30f, -1e30f};   // log2 domain
    float lsum[2] = {0.0f, 0.0f};

    const int aR = wm + (l & 15);
    const int bR = ((l >> 4) & 1) * 8 + (l & 7);
    const int bC = (l >> 3) & 1;
    const int vR = (l & 15);
    const int vC = (l >> 4);

    for (int j = 0; j < 32; ++j) {
        const int cur = j & 1;
        const uint32_t kb = sb + 32768 + cur * 16384;
        const uint32_t vb = sb + 65536 + cur * 8192;

        __syncthreads();   // buffer (j+1)&1 free (consumed in iter j-1)
        if (j + 1 < 32) {
            const int nxt = cur ^ 1;
            issue_k64(Kgh + (long)(j + 1) * 4096, Kgl + (long)(j + 1) * 4096,
                      sb + 32768 + nxt * 16384, tid);
            issue_v64(Vgh + (long)(j + 1) * 4096, sb + 65536 + nxt * 8192, tid);
            CP_COMMIT();
        }
        if (j < 31) { CP_WAIT(1); } else { CP_WAIT(0); }
        __syncthreads();

        // ---- S = Q K^T : warp tile 16 x 64, 3-MMA split ----
        float sacc[8][4];
        #pragma unroll
        for (int i = 0; i < 8; ++i)
            #pragma unroll
            for (int c = 0; c < 4; ++c) sacc[i][c] = 0.0f;

        #pragma unroll
        for (int ks = 0; ks < 4; ++ks) {
            uint32_t ah[4], al[4];
            {
                uint32_t off = (uint32_t)(aR * 128)
                             + (uint32_t)((((ks * 2 + (l >> 4)) ^ (aR & 7)) << 4));
                ldm_x4(ah, qb + off);
                ldm_x4(al, qb + 16384 + off);
            }
            #pragma unroll
            for (int nbp = 0; nbp < 4; nbp += 2) {
                uint32_t bh[2][4], bl[2][4];
                #pragma unroll
                for (int i = 0; i < 2; ++i) {
                    int row = (nbp + i) * 16 + bR;
                    uint32_t off = (uint32_t)(row * 128)
                                 + (uint32_t)((((ks * 2 + bC) ^ (row & 7)) << 4));
                    ldm_x4(bh[i], kb + off);
                    ldm_x4(bl[i], kb + 8192 + off);
                }
                #pragma unroll
                for (int i = 0; i < 2; ++i)
                    #pragma unroll
                    for (int nt2 = 0; nt2 < 2; ++nt2)
                        mma16816(sacc[(nbp + i) * 2 + nt2], ah,
                                 bh[i][nt2*2], bh[i][nt2*2+1]);
                #pragma unroll
                for (int i = 0; i < 2; ++i)
                    #pragma unroll
                    for (int nt2 = 0; nt2 < 2; ++nt2)
                        mma16816(sacc[(nbp + i) * 2 + nt2], ah,
                                 bl[i][nt2*2], bl[i][nt2*2+1]);
                #pragma unroll
                for (int i = 0; i < 2; ++i)
                    #pragma unroll
                    for (int nt2 = 0; nt2 < 2; ++nt2)
                        mma16816(sacc[(nbp + i) * 2 + nt2], al,
                                 bh[i][nt2*2], bh[i][nt2*2+1]);
            }
        }

        // ---- online softmax (log2 domain; rows h=0 -> l>>2, h=1 -> +8) ----
        float mnew[2] = {-1e30f, -1e30f};
        #pragma unroll
        for (int nt = 0; nt < 8; ++nt) {
            #pragma unroll
            for (int c = 0; c < 4; ++c) sacc[nt][c] *= SSCALE;
            mnew[0] = fmaxf(mnew[0], fmaxf(sacc[nt][0], sacc[nt][1]));
            mnew[1] = fmaxf(mnew[1], fmaxf(sacc[nt][2], sacc[nt][3]));
        }
        #pragma unroll
        for (int h = 0; h < 2; ++h) {
            mnew[h] = fmaxf(mnew[h], __shfl_xor_sync(0xffffffffu, mnew[h], 1));
            mnew[h] = fmaxf(mnew[h], __shfl_xor_sync(0xffffffffu, mnew[h], 2));
        }
        float corr[2];
        #pragma unroll
        for (int h = 0; h < 2; ++h) {
            float mi = fmaxf(mrun[h], mnew[h]);
            corr[h] = fexp2(mrun[h] - mi);
            mrun[h] = mi;
            lsum[h] *= corr[h];
        }
        float rs[2] = {0.0f, 0.0f};
        #pragma unroll
        for (int nt = 0; nt < 8; ++nt) {
            sacc[nt][0] = fexp2(sacc[nt][0] - mrun[0]);
            sacc[nt][1] = fexp2(sacc[nt][1] - mrun[0]);
            sacc[nt][2] = fexp2(sacc[nt][2] - mrun[1]);
            sacc[nt][3] = fexp2(sacc[nt][3] - mrun[1]);
            rs[0] += sacc[nt][0] + sacc[nt][1];
            rs[1] += sacc[nt][2] + sacc[nt][3];
        }
        #pragma unroll
        for (int h = 0; h < 2; ++h) {
            rs[h] += __shfl_xor_sync(0xffffffffu, rs[h], 1);
            rs[h] += __shfl_xor_sync(0xffffffffu, rs[h], 2);
            lsum[h] += rs[h];
        }
        #pragma unroll
        for (int nt = 0; nt < 8; ++nt) {
            oacc[nt][0] *= corr[0]; oacc[nt][1] *= corr[0];
            oacc[nt][2] *= corr[1]; oacc[nt][3] *= corr[1];
        }

        // ---- O += P V : 2-MMA (P split, V single) ----
        #pragma unroll
        for (int kt = 0; kt < 4; ++kt) {
            uint32_t ph[4], pl[4];
            ph[0] = packh(sacc[2*kt][0],   sacc[2*kt][1]);
            ph[1] = packh(sacc[2*kt][2],   sacc[2*kt][3]);
            ph[2] = packh(sacc[2*kt+1][0], sacc[2*kt+1][1]);
            ph[3] = packh(sacc[2*kt+1][2], sacc[2*kt+1][3]);
            pl[0] = packh_lo(sacc[2*kt][0],   sacc[2*kt][1],   ph[0]);
            pl[1] = packh_lo(sacc[2*kt][2],   sacc[2*kt][3],   ph[1]);
            pl[2] = packh_lo(sacc[2*kt+1][0], sacc[2*kt+1][1], ph[2]);
            pl[3] = packh_lo(sacc[2*kt+1][2], sacc[2*kt+1][3], ph[3]);
            #pragma unroll
            for (int npp = 0; npp < 4; npp += 2) {
                uint32_t vh[2][4];
                #pragma unroll
                for (int i = 0; i < 2; ++i) {
                    int row = kt * 16 + vR;
                    uint32_t off = (uint32_t)(row * 128)
                                 + (uint32_t)(((((npp + i) * 2 + vC) ^ (row & 7)) << 4));
                    ldm_x4_t(vh[i], vb + off);
                }
                // pass 1: ph x v
                #pragma unroll
                for (int i = 0; i < 2; ++i)
                    #pragma unroll
                    for (int d2 = 0; d2 < 2; ++d2)
                        mma16816(oacc[(npp + i) * 2 + d2], ph,
                                 vh[i][d2*2], vh[i][d2*2+1]);
                // pass 2: pl x v
                #pragma unroll
                for (int i = 0; i < 2; ++i)
                    #pragma unroll
                    for (int d2 = 0; d2 < 2; ++d2)
                        mma16816(oacc[(npp + i) * 2 + d2], pl,
                                 vh[i][d2*2], vh[i][d2*2+1]);
            }
        }
    }

    // ---- finalize: 1/l, Gram-Schmidt exclusion, fp16 hi/lo store [b,s,d] ----
    float inv[2] = {1.0f / lsum[0], 1.0f / lsum[1]};
    #pragma unroll
    for (int nt = 0; nt < 8; ++nt) {
        oacc[nt][0] *= inv[0]; oacc[nt][1] *= inv[0];
        oacc[nt][2] *= inv[1]; oacc[nt][3] *= inv[1];
    }

    const int bb = g >> 4, hh = g & 15;
    #pragma unroll
    for (int half = 0; half < 2; ++half) {
        int grow = m0 + wm + (l >> 2) + half * 8;
        const float* vr = VF + gbase + (long)grow * HD_;
        float vv[16];
        float dov = 0.0f, dvv = 0.0f;
        #pragma unroll
        for (int nt = 0; nt < 8; ++nt) {
            float2 t = *(const float2*)(vr + nt * 8 + (l & 3) * 2);
            vv[2*nt] = t.x; vv[2*nt+1] = t.y;
            float o0 = oacc[nt][half*2], o1 = oacc[nt][half*2+1];
            dov += o0 * t.x + o1 * t.y;
            dvv += t.x * t.x + t.y * t.y;
        }
        dov += __shfl_xor_sync(0xffffffffu, dov, 1);
        dov += __shfl_xor_sync(0xffffffffu, dov, 2);
        dvv += __shfl_xor_sync(0xffffffffu, dvv, 1);
        dvv += __shfl_xor_sync(0xffffffffu, dvv, 2);
        float al_ = dov / (dvv + 1e-8f);
        long obase = (long)(bb * S_ + grow) * D_ + hh * HD_;
        #pragma unroll
        for (int nt = 0; nt < 8; ++nt) {
            float rx = oacc[nt][half*2]   - al_ * vv[2*nt];
            float ry = oacc[nt][half*2+1] - al_ * vv[2*nt+1];
            long a = obase + nt * 8 + (l & 3) * 2;
            uint32_t hv = packh(rx, ry);
            *(uint32_t*)(OBh + a) = hv;
            *(uint32_t*)(OBl + a) = packh_lo(rx, ry, hv);
        }
    }
}

// ============================================================================
extern "C" void kernel_launch(void* const* d_in, const int* in_sizes, int n_in,
                              void* d_out, int out_size)
{
    const float* x  = (const float*)d_in[0];
    const float* wq = (const float*)d_in[1];
    const float* bq = (const float*)d_in[2];
    const float* wk = (const float*)d_in[3];
    const float* bk = (const float*)d_in[4];
    const float* wv = (const float*)d_in[5];
    const float* bv = (const float*)d_in[6];
    const float* wo = (const float*)d_in[7];
    const float* bo = (const float*)d_in[8];
    float* out = (float*)d_out;

    __half *xh, *xl, *wh, *wl, *qh, *ql, *kh, *kl, *vh, *obh, *obl;
    float *vf;
    cudaGetSymbolAddress((void**)&xh,  g_xh);
    cudaGetSymbolAddress((void**)&xl,  g_xl);
    cudaGetSymbolAddress((void**)&wh,  g_wh);
    cudaGetSymbolAddress((void**)&wl,  g_wl);
    cudaGetSymbolAddress((void**)&qh,  g_qh);
    cudaGetSymbolAddress((void**)&ql,  g_ql);
    cudaGetSymbolAddress((void**)&kh,  g_kh);
    cudaGetSymbolAddress((void**)&kl,  g_kl);
    cudaGetSymbolAddress((void**)&vh,  g_vh);
    cudaGetSymbolAddress((void**)&vf,  g_vf);
    cudaGetSymbolAddress((void**)&obh, g_obh);
    cudaGetSymbolAddress((void**)&obl, g_obl);

    const int SMG1 = 3 * 32768;    // 98304  (qkv, B split)
    const int SMG0 = 3 * 24576;    // 73728  (out, B single)
    const int SMF  = 81920;        // Q 32K + K 32K + V 16K
    cudaFuncSetAttribute(gemm_qkv,  cudaFuncAttributeMaxDynamicSharedMemorySize, SMG1);
    cudaFuncSetAttribute(gemm_out,  cudaFuncAttributeMaxDynamicSharedMemorySize, SMG0);
    cudaFuncSetAttribute(fused_attn, cudaFuncAttributeMaxDynamicSharedMemorySize, SMF);

    // 0) convert x + weights to fp16 hi/lo
    convert_all<<<dim3(512, 8), 256>>>(x, wq, wk, wv, wo, xh, xl, wh, wl);

    // 1) Q/K/V projections -> fp16 head layout (Q/K hi+lo, V hi + fp32)
    gemm_qkv<<<dim3(D_/128, M_/128, 3), 256, SMG1>>>(
        xh, xl, wh, wl, bq, bk, bv, qh, ql, kh, kl, vh, vf);

    // 2) fused attention + softmax + exclusion -> ob fp16 hi/lo [b,s,d]
    fused_attn<<<dim3(S_/128, G_), 256, SMF>>>(
        qh, ql, kh, kl, vh, vf, obh, obl);

    // 3) output projection (2-MMA, Wo single) -> d_out
    gemm_out<<<dim3(D_/128, M_/128, 1), 256, SMG0>>>(obh, obl, wh, bo, out);
}

// round 13
// speedup vs baseline: 1.9193x; 1.1118x over previous
#include <cuda_runtime.h>
#include <cuda_fp16.h>
#include <cstdint>

#define B_   2
#define S_   2048
#define D_   1024
#define H_   16
#define HD_  64
#define M_   (B_*S_)     // 4096
#define G_   (B_*H_)     // 32
#define NE_  ((size_t)M_*D_)   // 4194304

// ---- scratch (static device arrays; no allocation allowed) ----
__device__ __half g_xh[NE_], g_xl[NE_];      // x fp16 hi/lo
__device__ __half g_wh[NE_], g_wl[NE_];      // wq|wk|wv|wo hi/lo
__device__ __half g_qh[NE_];                 // Q head layout (single plane)
__device__ __half g_kh[NE_], g_kl[NE_];      // K split
__device__ __half g_vh[NE_];                 // V fp16 (single plane)
__device__ float  g_vf[NE_];                 // V fp32 (exclusion)
__device__ __half g_obh[NE_], g_obl[NE_];    // attn out [b,s,d]

// ============================================================================
// helpers
// ============================================================================
__device__ __forceinline__ uint32_t smem_u32(const void* p) {
    uint32_t a;
    asm("{ .reg .u64 t; cvta.to.shared.u64 t, %1; cvt.u32.u64 %0, t; }"
        : "=r"(a) : "l"(p));
    return a;
}
__device__ __forceinline__ void ldm_x4(uint32_t* r, uint32_t addr) {
    asm volatile("ldmatrix.sync.aligned.m8n8.x4.shared.b16 {%0,%1,%2,%3}, [%4];"
        : "=r"(r[0]), "=r"(r[1]), "=r"(r[2]), "=r"(r[3]) : "r"(addr));
}
__device__ __forceinline__ void ldm_x4_t(uint32_t* r, uint32_t addr) {
    asm volatile("ldmatrix.sync.aligned.m8n8.x4.trans.shared.b16 {%0,%1,%2,%3}, [%4];"
        : "=r"(r[0]), "=r"(r[1]), "=r"(r[2]), "=r"(r[3]) : "r"(addr));
}
__device__ __forceinline__ void mma16816(float* c, const uint32_t* a,
                                         uint32_t b0, uint32_t b1) {
    asm volatile(
        "mma.sync.aligned.m16n8k16.row.col.f32.f16.f16.f32 "
        "{%0,%1,%2,%3}, {%4,%5,%6,%7}, {%8,%9}, {%0,%1,%2,%3};"
        : "+f"(c[0]), "+f"(c[1]), "+f"(c[2]), "+f"(c[3])
        : "r"(a[0]), "r"(a[1]), "r"(a[2]), "r"(a[3]), "r"(b0), "r"(b1));
}
__device__ __forceinline__ uint32_t packh(float x, float y) {
    __half2 t = __floats2half2_rn(x, y);
    return *(uint32_t*)&t;
}
__device__ __forceinline__ uint32_t packh_lo(float x, float y, uint32_t hi) {
    __half2 h = *(__half2*)&hi;
    return packh(x - __half2float(h.x), y - __half2float(h.y));
}
__device__ __forceinline__ float fexp2(float x) {
    float y;
    asm("ex2.approx.f32 %0, %1;" : "=f"(y) : "f"(x));
    return y;
}
__device__ __forceinline__ void cpa(uint32_t dst, const void* src) {
    asm volatile("cp.async.cg.shared.global [%0], [%1], 16;"
        :: "r"(dst), "l"(src) : "memory");
}
#define CP_COMMIT() asm volatile("cp.async.commit_group;" ::: "memory")
#define CP_WAIT(n)  asm volatile("cp.async.wait_group %0;" :: "n"(n) : "memory")

// 0.125 (1/sqrt(64)) * log2(e)  -> softmax run in log2 domain
#define SSCALE 0.18033688f

// ============================================================================
// Convert pass: x (4 quarters) + 4 weights -> fp16 hi/lo
// ============================================================================
__global__ void __launch_bounds__(256)
convert_all(const float* __restrict__ x,
            const float* __restrict__ wq, const float* __restrict__ wk,
            const float* __restrict__ wv, const float* __restrict__ wo,
            __half* __restrict__ xh, __half* __restrict__ xl,
            __half* __restrict__ wh, __half* __restrict__ wl)
{
    const int z = blockIdx.y;
    const float* src;
    __half *dh, *dl;
    if (z < 4) {
        src = x  + ((long)z << 20);
        dh  = xh + ((long)z << 20);
        dl  = xl + ((long)z << 20);
    } else {
        const float* ws = (z == 4) ? wq : (z == 5) ? wk : (z == 6) ? wv : wo;
        src = ws;
        dh  = wh + ((long)(z - 4) << 20);
        dl  = wl + ((long)(z - 4) << 20);
    }
    long i = ((long)blockIdx.x * 256 + threadIdx.x) * 8;
    float4 a = *(const float4*)(src + i);
    float4 b = *(const float4*)(src + i + 4);
    uint32_t h0 = packh(a.x, a.y), h1 = packh(a.z, a.w);
    uint32_t h2 = packh(b.x, b.y), h3 = packh(b.z, b.w);
    uint32_t l0 = packh_lo(a.x, a.y, h0), l1 = packh_lo(a.z, a.w, h1);
    uint32_t l2 = packh_lo(b.x, b.y, h2), l3 = packh_lo(b.z, b.w, h3);
    *(uint4*)(dh + i) = make_uint4(h0, h1, h2, h3);
    *(uint4*)(dl + i) = make_uint4(l0, l1, l2, l3);
}

// ============================================================================
// fp16 cp.async GEMM: C = A W^T (+bias). BM=BN=128, BK=32, 3-stage pipeline.
// BS=1: B split hi/lo, 3-MMA (hh, hl, lh). Stage 32KB.
// BS=0: B single,      2-MMA (hh, lh).     Stage 24KB.
// ============================================================================
template<int BS>
__device__ __forceinline__ void gemm_issue(
    const __half* __restrict__ Ah, const __half* __restrict__ Al,
    const __half* __restrict__ Wh, const __half* __restrict__ Wl,
    int m0, int n0, int s, uint32_t sb, int tid)
{
    const int kc = s * 32;
    const uint32_t STGB = BS ? 32768u : 24576u;
    const uint32_t stb = sb + (uint32_t)(s % 3) * STGB;
    constexpr int ITERS = BS ? 8 : 6;
    #pragma unroll
    for (int it = 0; it < ITERS; ++it) {
        int idx  = tid + it * 256;
        int bsel = idx >> 9;                 // 0=Ah 1=Al 2=Wh (3=Wl if BS)
        int ci   = idx & 511;
        int row  = ci >> 2, ch = ci & 3;
        const __half* src =
            (bsel == 0) ? Ah + (long)(m0 + row) * 1024 + kc + ch * 8 :
            (bsel == 1) ? Al + (long)(m0 + row) * 1024 + kc + ch * 8 :
            (bsel == 2) ? Wh + (long)(n0 + row) * 1024 + kc + ch * 8 :
                          Wl + (long)(n0 + row) * 1024 + kc + ch * 8;
        uint32_t dst = stb + (uint32_t)(bsel * 8192) + (uint32_t)(row * 64)
                     + (uint32_t)(((ch ^ ((row >> 1) & 3)) << 4));
        cpa(dst, src);
    }
}

template<int MODE, int BS>
__device__ __forceinline__ void gemm_async(
    const __half* __restrict__ Ah, const __half* __restrict__ Al,
    const __half* __restrict__ Wh, const __half* __restrict__ Wl,
    const float* __restrict__ bias,
    float* __restrict__ Cf,
    __half* __restrict__ Oh, __half* __restrict__ Ol,
    float* __restrict__ Of,
    char* smem)
{
    const int tid = threadIdx.x;
    const int wid = tid >> 5;
    const int l   = tid & 31;
    const int m0  = blockIdx.y * 128;
    const int n0  = blockIdx.x * 128;
    const int wm  = (wid / 4) * 64;
    const int wn  = (wid % 4) * 32;

    const int aRow = (l & 15);
    const int aCk  = (l >> 4);
    const int bRow = ((l >> 4) & 1) * 8 + (l & 7);
    const int bCk  = (l >> 3) & 1;
    const uint32_t STGB = BS ? 32768u : 24576u;

    float acc[4][4][4];
    #pragma unroll
    for (int a = 0; a < 4; ++a)
        #pragma unroll
        for (int b = 0; b < 4; ++b)
            #pragma unroll
            for (int c = 0; c < 4; ++c) acc[a][b][c] = 0.0f;

    const uint32_t sb = smem_u32(smem);

    gemm_issue<BS>(Ah, Al, Wh, Wl, m0, n0, 0, sb, tid); CP_COMMIT();
    gemm_issue<BS>(Ah, Al, Wh, Wl, m0, n0, 1, sb, tid); CP_COMMIT();

    for (int c = 0; c < 32; ++c) {
        if (c < 31) { CP_WAIT(1); } else { CP_WAIT(0); }
        __syncthreads();
        if (c + 2 < 32) {
            gemm_issue<BS>(Ah, Al, Wh, Wl, m0, n0, c + 2, sb, tid);
            CP_COMMIT();
        }

        const uint32_t stb = sb + (uint32_t)(c % 3) * STGB;
        const uint32_t ahi = stb;
        const uint32_t alo = stb + 8192;
        const uint32_t bhi = stb + 16384;
        const uint32_t blo = stb + 24576;    // only valid when BS=1

        #pragma unroll
        for (int ks = 0; ks < 2; ++ks) {
            uint32_t ah[4][4], al[4][4], bh[2][4], bl[2][4];
            #pragma unroll
            for (int mt = 0; mt < 4; ++mt) {
                int row = wm + mt * 16 + aRow;
                uint32_t off = (uint32_t)(row * 64)
                             + (uint32_t)((((2*ks + aCk) ^ ((row >> 1) & 3)) << 4));
                ldm_x4(ah[mt], ahi + off);
                ldm_x4(al[mt], alo + off);
            }
            #pragma unroll
            for (int nb = 0; nb < 2; ++nb) {
                int row = wn + nb * 16 + bRow;
                uint32_t off = (uint32_t)(row * 64)
                             + (uint32_t)((((2*ks + bCk) ^ ((row >> 1) & 3)) << 4));
                ldm_x4(bh[nb], bhi + off);
                if (BS) ldm_x4(bl[nb], blo + off);
            }
            // pass 1: ah x bh
            #pragma unroll
            for (int mt = 0; mt < 4; ++mt)
                #pragma unroll
                for (int nt = 0; nt < 4; ++nt) {
                    const uint32_t* pb = &bh[nt >> 1][(nt & 1) * 2];
                    mma16816(acc[mt][nt], ah[mt], pb[0], pb[1]);
                }
            // pass 2 (BS only): ah x bl
            if (BS) {
                #pragma unroll
                for (int mt = 0; mt < 4; ++mt)
                    #pragma unroll
                    for (int nt = 0; nt < 4; ++nt) {
                        const uint32_t* pb = &bl[nt >> 1][(nt & 1) * 2];
                        mma16816(acc[mt][nt], ah[mt], pb[0], pb[1]);
                    }
            }
            // pass 3: al x bh
            #pragma unroll
            for (int mt = 0; mt < 4; ++mt)
                #pragma unroll
                for (int nt = 0; nt < 4; ++nt) {
                    const uint32_t* pb = &bh[nt >> 1][(nt & 1) * 2];
                    mma16816(acc[mt][nt], al[mt], pb[0], pb[1]);
                }
        }
    }

    #pragma unroll
    for (int mt = 0; mt < 4; ++mt) {
        #pragma unroll
        for (int nt = 0; nt < 4; ++nt) {
            int n = n0 + wn + nt * 8 + (l & 3) * 2;
            float2 bb = *(const float2*)(bias + n);
            #pragma unroll
            for (int half = 0; half < 2; ++half) {
                int m = m0 + wm + mt * 16 + (l >> 2) + half * 8;
                float2 r;
                r.x = acc[mt][nt][half*2]   + bb.x;
                r.y = acc[mt][nt][half*2+1] + bb.y;
                if (MODE == 0) {
                    *(float2*)(Cf + (long)m * 1024 + n) = r;
                } else {
                    int b2 = m >> 11, s = m & 2047;
                    int h = n >> 6, hd = n & 63;
                    long addr = ((long)(b2 * H_ + h) * S_ + s) * HD_ + hd;
                    uint32_t hv = packh(r.x, r.y);
                    *(uint32_t*)(Oh + addr) = hv;
                    if (Ol) *(uint32_t*)(Ol + addr) = packh_lo(r.x, r.y, hv);
                    if (Of) *(float2*)(Of + addr) = r;
                }
            }
        }
    }
}

// K projection: 3-MMA (K stays split downstream)
__global__ void __launch_bounds__(256, 2)
gemm_k(const __half* __restrict__ xh, const __half* __restrict__ xl,
       const __half* __restrict__ wh, const __half* __restrict__ wl,
       const float* __restrict__ bk,
       __half* __restrict__ kh, __half* __restrict__ kl)
{
    extern __shared__ char smem[];
    gemm_async<1, 1>(xh, xl, wh + (1L << 20), wl + (1L << 20),
                     bk, nullptr, kh, kl, nullptr, smem);
}

// Q and V projections: 2-MMA (outputs consumed as fp16-single downstream)
__global__ void __launch_bounds__(256, 2)
gemm_qv(const __half* __restrict__ xh, const __half* __restrict__ xl,
        const __half* __restrict__ wh,
        const float* __restrict__ bq, const float* __restrict__ bv,
        __half* __restrict__ qh, __half* __restrict__ vh,
        float* __restrict__ vf)
{
    extern __shared__ char smem[];
    const int z = blockIdx.z;                 // 0=Q, 2-plane offset picks wq/wv
    const __half* Wh = wh + ((long)(z == 0 ? 0 : 2) << 20);
    const float* bias = (z == 0) ? bq : bv;
    __half* Oh = (z == 0) ? qh : vh;
    float* Of = (z == 0) ? nullptr : vf;
    gemm_async<1, 0>(xh, xl, Wh, nullptr, bias, nullptr, Oh, nullptr, Of, smem);
}

__global__ void __launch_bounds__(256, 2)
gemm_out(const __half* __restrict__ ah, const __half* __restrict__ al,
         const __half* __restrict__ wh,
         const float* __restrict__ bias, float* __restrict__ C)
{
    extern __shared__ char smem[];
    gemm_async<0, 0>(ah, al, wh + ((long)3 << 20), nullptr,
                     bias, C, nullptr, nullptr, nullptr, smem);
}

// ============================================================================
// Fused attention, 2 CTAs/SM: KV block 64 rows, 32 iterations.
// smem: Q 16K (single) | K 2x16K (hi+lo) | V 2x8K (single) = 64 KB.
// QK^T: 2-MMA (Q single, K split). PV: 2-MMA (P split, V single).
// ============================================================================
__device__ __forceinline__ void issue_q(const __half* __restrict__ Gh,
    uint32_t dst, int tid)
{
    #pragma unroll
    for (int it = 0; it < 4; ++it) {
        int idx = tid + it * 256;
        int row = idx >> 3, ch = idx & 7;
        uint32_t off = (uint32_t)(row * 128) + (uint32_t)(((ch ^ (row & 7)) << 4));
        cpa(dst + off, Gh + row * 64 + ch * 8);
    }
}
__device__ __forceinline__ void issue_k64(const __half* __restrict__ Gh,
    const __half* __restrict__ Gl, uint32_t dst_hi, int tid)
{
    #pragma unroll
    for (int it = 0; it < 2; ++it) {
        int idx = tid + it * 256;       // 0..511
        int row = idx >> 3, ch = idx & 7;
        uint32_t off = (uint32_t)(row * 128) + (uint32_t)(((ch ^ (row & 7)) << 4));
        cpa(dst_hi + off,        Gh + row * 64 + ch * 8);
        cpa(dst_hi + 8192 + off, Gl + row * 64 + ch * 8);
    }
}
__device__ __forceinline__ void issue_v64(const __half* __restrict__ Gh,
    uint32_t dst, int tid)
{
    #pragma unroll
    for (int it = 0; it < 2; ++it) {
        int idx = tid + it * 256;       // 0..511
        int row = idx >> 3, ch = idx & 7;
        uint32_t off = (uint32_t)(row * 128) + (uint32_t)(((ch ^ (row & 7)) << 4));
        cpa(dst + off, Gh + row * 64 + ch * 8);
    }
}

__global__ void __launch_bounds__(256, 2)
fused_attn(const __half* __restrict__ Qh,
           const __half* __restrict__ Kh, const __half* __restrict__ Kl,
           const __half* __restrict__ Vh, const float* __restrict__ VF,
           __half* __restrict__ OBh, __half* __restrict__ OBl)
{
    extern __shared__ char sm[];
    const int tid = threadIdx.x;
    const int wid = tid >> 5;
    const int l   = tid & 31;
    const int g   = blockIdx.y;
    const int m0  = blockIdx.x * 128;
    const int wm  = wid * 16;

    const long gbase = (long)g * S_ * HD_;
    const __half* Kgh = Kh + gbase;
    const __half* Kgl = Kl + gbase;
    const __half* Vgh = Vh + gbase;

    const uint32_t sb = smem_u32(sm);
    const uint32_t qb = sb;                 // Q single plane, 16K
    // K buffers @16384 + cur*16384 (hi, lo@+8192); V @49152 + cur*8192

    // prologue: Q + K0 + V0 as group 0
    issue_q(Qh + gbase + (long)m0 * HD_, sb, tid);
    issue_k64(Kgh, Kgl, sb + 16384, tid);
    issue_v64(Vgh, sb + 49152, tid);
    CP_COMMIT();

    float oacc[8][4];
    #pragma unroll
    for (int i = 0; i < 8; ++i)
        #pragma unroll
        for (int j = 0; j < 4; ++j) oacc[i][j] = 0.0f;
    float mrun[2] = {-1e30f, -1e30f};   // log2 domain
    float lsum[2] = {0.0f, 0.0f};

    const int aR = wm + (l & 15);
    const int bR = ((l >> 4) & 1) * 8 + (l & 7);
    const int bC = (l >> 3) & 1;
    const int vR = (l & 15);
    const int vC = (l >> 4);

    for (int j = 0; j < 32; ++j) {
        const int cur = j & 1;
        const uint32_t kb = sb + 16384 + cur * 16384;
        const uint32_t vb = sb + 49152 + cur * 8192;

        __syncthreads();   // buffer (j+1)&1 free (consumed in iter j-1)
        if (j + 1 < 32) {
            const int nxt = cur ^ 1;
            issue_k64(Kgh + (long)(j + 1) * 4096, Kgl + (long)(j + 1) * 4096,
                      sb + 16384 + nxt * 16384, tid);
            issue_v64(Vgh + (long)(j + 1) * 4096, sb + 49152 + nxt * 8192, tid);
            CP_COMMIT();
        }
        if (j < 31) { CP_WAIT(1); } else { CP_WAIT(0); }
        __syncthreads();

        // ---- S = Q K^T : warp tile 16 x 64, 2-MMA (Q single, K split) ----
        float sacc[8][4];
        #pragma unroll
        for (int i = 0; i < 8; ++i)
            #pragma unroll
            for (int c = 0; c < 4; ++c) sacc[i][c] = 0.0f;

        #pragma unroll
        for (int ks = 0; ks < 4; ++ks) {
            uint32_t ah[4];
            {
                uint32_t off = (uint32_t)(aR * 128)
                             + (uint32_t)((((ks * 2 + (l >> 4)) ^ (aR & 7)) << 4));
                ldm_x4(ah, qb + off);
            }
            #pragma unroll
            for (int nbp = 0; nbp < 4; nbp += 2) {
                uint32_t bh[2][4], bl[2][4];
                #pragma unroll
                for (int i = 0; i < 2; ++i) {
                    int row = (nbp + i) * 16 + bR;
                    uint32_t off = (uint32_t)(row * 128)
                                 + (uint32_t)((((ks * 2 + bC) ^ (row & 7)) << 4));
                    ldm_x4(bh[i], kb + off);
                    ldm_x4(bl[i], kb + 8192 + off);
                }
                // pass 1: q x kh
                #pragma unroll
                for (int i = 0; i < 2; ++i)
                    #pragma unroll
                    for (int nt2 = 0; nt2 < 2; ++nt2)
                        mma16816(sacc[(nbp + i) * 2 + nt2], ah,
                                 bh[i][nt2*2], bh[i][nt2*2+1]);
                // pass 2: q x kl
                #pragma unroll
                for (int i = 0; i < 2; ++i)
                    #pragma unroll
                    for (int nt2 = 0; nt2 < 2; ++nt2)
                        mma16816(sacc[(nbp + i) * 2 + nt2], ah,
                                 bl[i][nt2*2], bl[i][nt2*2+1]);
            }
        }

        // ---- online softmax (log2 domain; rows h=0 -> l>>2, h=1 -> +8) ----
        float mnew[2] = {-1e30f, -1e30f};
        #pragma unroll
        for (int nt = 0; nt < 8; ++nt) {
            #pragma unroll
            for (int c = 0; c < 4; ++c) sacc[nt][c] *= SSCALE;
            mnew[0] = fmaxf(mnew[0], fmaxf(sacc[nt][0], sacc[nt][1]));
            mnew[1] = fmaxf(mnew[1], fmaxf(sacc[nt][2], sacc[nt][3]));
        }
        #pragma unroll
        for (int h = 0; h < 2; ++h) {
            mnew[h] = fmaxf(mnew[h], __shfl_xor_sync(0xffffffffu, mnew[h], 1));
            mnew[h] = fmaxf(mnew[h], __shfl_xor_sync(0xffffffffu, mnew[h], 2));
        }
        float corr[2];
        #pragma unroll
        for (int h = 0; h < 2; ++h) {
            float mi = fmaxf(mrun[h], mnew[h]);
            corr[h] = fexp2(mrun[h] - mi);
            mrun[h] = mi;
            lsum[h] *= corr[h];
        }
        float rs[2] = {0.0f, 0.0f};
        #pragma unroll
        for (int nt = 0; nt < 8; ++nt) {
            sacc[nt][0] = fexp2(sacc[nt][0] - mrun[0]);
            sacc[nt][1] = fexp2(sacc[nt][1] - mrun[0]);
            sacc[nt][2] = fexp2(sacc[nt][2] - mrun[1]);
            sacc[nt][3] = fexp2(sacc[nt][3] - mrun[1]);
            rs[0] += sacc[nt][0] + sacc[nt][1];
            rs[1] += sacc[nt][2] + sacc[nt][3];
        }
        #pragma unroll
        for (int h = 0; h < 2; ++h) {
            rs[h] += __shfl_xor_sync(0xffffffffu, rs[h], 1);
            rs[h] += __shfl_xor_sync(0xffffffffu, rs[h], 2);
            lsum[h] += rs[h];
        }
        #pragma unroll
        for (int nt = 0; nt < 8; ++nt) {
            oacc[nt][0] *= corr[0]; oacc[nt][1] *= corr[0];
            oacc[nt][2] *= corr[1]; oacc[nt][3] *= corr[1];
        }

        // ---- O += P V : 2-MMA (P split, V single) ----
        #pragma unroll
        for (int kt = 0; kt < 4; ++kt) {
            uint32_t ph[4], pl[4];
            ph[0] = packh(sacc[2*kt][0],   sacc[2*kt][1]);
            ph[1] = packh(sacc[2*kt][2],   sacc[2*kt][3]);
            ph[2] = packh(sacc[2*kt+1][0], sacc[2*kt+1][1]);
            ph[3] = packh(sacc[2*kt+1][2], sacc[2*kt+1][3]);
            pl[0] = packh_lo(sacc[2*kt][0],   sacc[2*kt][1],   ph[0]);
            pl[1] = packh_lo(sacc[2*kt][2],   sacc[2*kt][3],   ph[1]);
            pl[2] = packh_lo(sacc[2*kt+1][0], sacc[2*kt+1][1], ph[2]);
            pl[3] = packh_lo(sacc[2*kt+1][2], sacc[2*kt+1][3], ph[3]);
            #pragma unroll
            for (int npp = 0; npp < 4; npp += 2) {
                uint32_t vh[2][4];
                #pragma unroll
                for (int i = 0; i < 2; ++i) {
                    int row = kt * 16 + vR;
                    uint32_t off = (uint32_t)(row * 128)
                                 + (uint32_t)(((((npp + i) * 2 + vC) ^ (row & 7)) << 4));
                    ldm_x4_t(vh[i], vb + off);
                }
                // pass 1: ph x v
                #pragma unroll
                for (int i = 0; i < 2; ++i)
                    #pragma unroll
                    for (int d2 = 0; d2 < 2; ++d2)
                        mma16816(oacc[(npp + i) * 2 + d2], ph,
                                 vh[i][d2*2], vh[i][d2*2+1]);
                // pass 2: pl x v
                #pragma unroll
                for (int i = 0; i < 2; ++i)
                    #pragma unroll
                    for (int d2 = 0; d2 < 2; ++d2)
                        mma16816(oacc[(npp + i) * 2 + d2], pl,
                                 vh[i][d2*2], vh[i][d2*2+1]);
            }
        }
    }

    // ---- finalize: 1/l, Gram-Schmidt exclusion, fp16 hi/lo store [b,s,d] ----
    float inv[2] = {1.0f / lsum[0], 1.0f / lsum[1]};
    #pragma unroll
    for (int nt = 0; nt < 8; ++nt) {
        oacc[nt][0] *= inv[0]; oacc[nt][1] *= inv[0];
        oacc[nt][2] *= inv[1]; oacc[nt][3] *= inv[1];
    }

    const int bb = g >> 4, hh = g & 15;
    #pragma unroll
    for (int half = 0; half < 2; ++half) {
        int grow = m0 + wm + (l >> 2) + half * 8;
        const float* vr = VF + gbase + (long)grow * HD_;
        float vv[16];
        float dov = 0.0f, dvv = 0.0f;
        #pragma unroll
        for (int nt = 0; nt < 8; ++nt) {
            float2 t = *(const float2*)(vr + nt * 8 + (l & 3) * 2);
            vv[2*nt] = t.x; vv[2*nt+1] = t.y;
            float o0 = oacc[nt][half*2], o1 = oacc[nt][half*2+1];
            dov += o0 * t.x + o1 * t.y;
            dvv += t.x * t.x + t.y * t.y;
        }
        dov += __shfl_xor_sync(0xffffffffu, dov, 1);
        dov += __shfl_xor_sync(0xffffffffu, dov, 2);
        dvv += __shfl_xor_sync(0xffffffffu, dvv, 1);
        dvv += __shfl_xor_sync(0xffffffffu, dvv, 2);
        float al_ = dov / (dvv + 1e-8f);
        long obase = (long)(bb * S_ + grow) * D_ + hh * HD_;
        #pragma unroll
        for (int nt = 0; nt < 8; ++nt) {
            float rx = oacc[nt][half*2]   - al_ * vv[2*nt];
            float ry = oacc[nt][half*2+1] - al_ * vv[2*nt+1];
            long a = obase + nt * 8 + (l & 3) * 2;
            uint32_t hv = packh(rx, ry);
            *(uint32_t*)(OBh + a) = hv;
            *(uint32_t*)(OBl + a) = packh_lo(rx, ry, hv);
        }
    }
}

// ============================================================================
extern "C" void kernel_launch(void* const* d_in, const int* in_sizes, int n_in,
                              void* d_out, int out_size)
{
    const float* x  = (const float*)d_in[0];
    const float* wq = (const float*)d_in[1];
    const float* bq = (const float*)d_in[2];
    const float* wk = (const float*)d_in[3];
    const float* bk = (const float*)d_in[4];
    const float* wv = (const float*)d_in[5];
    const float* bv = (const float*)d_in[6];
    const float* wo = (const float*)d_in[7];
    const float* bo = (const float*)d_in[8];
    float* out = (float*)d_out;

    __half *xh, *xl, *wh, *wl, *qh, *kh, *kl, *vh, *obh, *obl;
    float *vf;
    cudaGetSymbolAddress((void**)&xh,  g_xh);
    cudaGetSymbolAddress((void**)&xl,  g_xl);
    cudaGetSymbolAddress((void**)&wh,  g_wh);
    cudaGetSymbolAddress((void**)&wl,  g_wl);
    cudaGetSymbolAddress((void**)&qh,  g_qh);
    cudaGetSymbolAddress((void**)&kh,  g_kh);
    cudaGetSymbolAddress((void**)&kl,  g_kl);
    cudaGetSymbolAddress((void**)&vh,  g_vh);
    cudaGetSymbolAddress((void**)&vf,  g_vf);
    cudaGetSymbolAddress((void**)&obh, g_obh);
    cudaGetSymbolAddress((void**)&obl, g_obl);

    const int SMG1 = 3 * 32768;    // 98304  (K proj, B split)
    const int SMG0 = 3 * 24576;    // 73728  (Q/V proj + out, B single)
    const int SMF  = 65536;        // Q 16K + K 32K + V 16K
    cudaFuncSetAttribute(gemm_k,   cudaFuncAttributeMaxDynamicSharedMemorySize, SMG1);
    cudaFuncSetAttribute(gemm_qv,  cudaFuncAttributeMaxDynamicSharedMemorySize, SMG0);
    cudaFuncSetAttribute(gemm_out, cudaFuncAttributeMaxDynamicSharedMemorySize, SMG0);
    cudaFuncSetAttribute(fused_attn, cudaFuncAttributeMaxDynamicSharedMemorySize, SMF);

    // 0) convert x + weights to fp16 hi/lo
    convert_all<<<dim3(512, 8), 256>>>(x, wq, wk, wv, wo, xh, xl, wh, wl);

    // 1) projections: K (3-MMA, split out), Q+V (2-MMA, single out)
    gemm_k <<<dim3(D_/128, M_/128, 1), 256, SMG1>>>(xh, xl, wh, wl, bk, kh, kl);
    gemm_qv<<<dim3(D_/128, M_/128, 2), 256, SMG0>>>(xh, xl, wh, bq, bv, qh, vh, vf);

    // 2) fused attention + softmax + exclusion -> ob fp16 hi/lo [b,s,d]
    fused_attn<<<dim3(S_/128, G_), 256, SMF>>>(qh, kh, kl, vh, vf, obh, obl);

    // 3) output projection (2-MMA, Wo single) -> d_out
    gemm_out<<<dim3(D_/128, M_/128, 1), 256, SMG0>>>(obh, obl, wh, bo, out);
}

// round 14
// speedup vs baseline: 2.2018x; 1.1472x over previous
#include <cuda_runtime.h>
#include <cuda_fp16.h>
#include <cstdint>

#define B_   2
#define S_   2048
#define D_   1024
#define H_   16
#define HD_  64
#define M_   (B_*S_)     // 4096
#define G_   (B_*H_)     // 32
#define NE_  ((size_t)M_*D_)   // 4194304

// ---- scratch (static device arrays; no allocation allowed) ----
__device__ __half g_xh[NE_], g_xl[NE_];      // x fp16 hi/lo
__device__ __half g_wh[NE_], g_wl[NE_];      // wq|wk|wv|wo hi/lo
__device__ __half g_qh[NE_];                 // Q head layout (single, pre-scaled)
__device__ __half g_kh[NE_], g_kl[NE_];      // K split
__device__ __half g_vh[NE_];                 // V fp16 (single plane)
__device__ float  g_vf[NE_];                 // V fp32 (exclusion)
__device__ __half g_obh[NE_], g_obl[NE_];    // attn out [b,s,d]

// ============================================================================
// helpers
// ============================================================================
__device__ __forceinline__ uint32_t smem_u32(const void* p) {
    uint32_t a;
    asm("{ .reg .u64 t; cvta.to.shared.u64 t, %1; cvt.u32.u64 %0, t; }"
        : "=r"(a) : "l"(p));
    return a;
}
__device__ __forceinline__ void ldm_x4(uint32_t* r, uint32_t addr) {
    asm volatile("ldmatrix.sync.aligned.m8n8.x4.shared.b16 {%0,%1,%2,%3}, [%4];"
        : "=r"(r[0]), "=r"(r[1]), "=r"(r[2]), "=r"(r[3]) : "r"(addr));
}
__device__ __forceinline__ void ldm_x4_t(uint32_t* r, uint32_t addr) {
    asm volatile("ldmatrix.sync.aligned.m8n8.x4.trans.shared.b16 {%0,%1,%2,%3}, [%4];"
        : "=r"(r[0]), "=r"(r[1]), "=r"(r[2]), "=r"(r[3]) : "r"(addr));
}
__device__ __forceinline__ void mma16816(float* c, const uint32_t* a,
                                         uint32_t b0, uint32_t b1) {
    asm volatile(
        "mma.sync.aligned.m16n8k16.row.col.f32.f16.f16.f32 "
        "{%0,%1,%2,%3}, {%4,%5,%6,%7}, {%8,%9}, {%0,%1,%2,%3};"
        : "+f"(c[0]), "+f"(c[1]), "+f"(c[2]), "+f"(c[3])
        : "r"(a[0]), "r"(a[1]), "r"(a[2]), "r"(a[3]), "r"(b0), "r"(b1));
}
__device__ __forceinline__ uint32_t packh(float x, float y) {
    __half2 t = __floats2half2_rn(x, y);
    return *(uint32_t*)&t;
}
__device__ __forceinline__ uint32_t packh_lo(float x, float y, uint32_t hi) {
    __half2 h = *(__half2*)&hi;
    return packh(x - __half2float(h.x), y - __half2float(h.y));
}
__device__ __forceinline__ float fexp2(float x) {
    float y;
    asm("ex2.approx.f32 %0, %1;" : "=f"(y) : "f"(x));
    return y;
}
__device__ __forceinline__ void cpa(uint32_t dst, const void* src) {
    asm volatile("cp.async.cg.shared.global [%0], [%1], 16;"
        :: "r"(dst), "l"(src) : "memory");
}
#define CP_COMMIT() asm volatile("cp.async.commit_group;" ::: "memory")
#define CP_WAIT(n)  asm volatile("cp.async.wait_group %0;" :: "n"(n) : "memory")

// 0.125 (1/sqrt(64)) * log2(e)  -> softmax run in log2 domain (folded into Q)
#define SSCALE 0.18033688f

// ============================================================================
// Convert pass: x (4 quarters) + 4 weights -> fp16 hi/lo
// ============================================================================
__global__ void __launch_bounds__(256)
convert_all(const float* __restrict__ x,
            const float* __restrict__ wq, const float* __restrict__ wk,
            const float* __restrict__ wv, const float* __restrict__ wo,
            __half* __restrict__ xh, __half* __restrict__ xl,
            __half* __restrict__ wh, __half* __restrict__ wl)
{
    const int z = blockIdx.y;
    const float* src;
    __half *dh, *dl;
    if (z < 4) {
        src = x  + ((long)z << 20);
        dh  = xh + ((long)z << 20);
        dl  = xl + ((long)z << 20);
    } else {
        const float* ws = (z == 4) ? wq : (z == 5) ? wk : (z == 6) ? wv : wo;
        src = ws;
        dh  = wh + ((long)(z - 4) << 20);
        dl  = wl + ((long)(z - 4) << 20);
    }
    long i = ((long)blockIdx.x * 256 + threadIdx.x) * 8;
    float4 a = *(const float4*)(src + i);
    float4 b = *(const float4*)(src + i + 4);
    uint32_t h0 = packh(a.x, a.y), h1 = packh(a.z, a.w);
    uint32_t h2 = packh(b.x, b.y), h3 = packh(b.z, b.w);
    uint32_t l0 = packh_lo(a.x, a.y, h0), l1 = packh_lo(a.z, a.w, h1);
    uint32_t l2 = packh_lo(b.x, b.y, h2), l3 = packh_lo(b.z, b.w, h3);
    *(uint4*)(dh + i) = make_uint4(h0, h1, h2, h3);
    *(uint4*)(dl + i) = make_uint4(l0, l1, l2, l3);
}

// ============================================================================
// fp16 cp.async GEMM: C = oscale*(A W^T + bias). BM=BN=128, BK=32, 3-stage.
// BS=1: B split hi/lo, 3-MMA. Stage 32KB.  BS=0: B single, 2-MMA. Stage 24KB.
// ============================================================================
template<int BS>
__device__ __forceinline__ void gemm_issue(
    const __half* __restrict__ Ah, const __half* __restrict__ Al,
    const __half* __restrict__ Wh, const __half* __restrict__ Wl,
    int m0, int n0, int s, uint32_t sb, int tid)
{
    const int kc = s * 32;
    const uint32_t STGB = BS ? 32768u : 24576u;
    const uint32_t stb = sb + (uint32_t)(s % 3) * STGB;
    constexpr int ITERS = BS ? 8 : 6;
    #pragma unroll
    for (int it = 0; it < ITERS; ++it) {
        int idx  = tid + it * 256;
        int bsel = idx >> 9;                 // 0=Ah 1=Al 2=Wh (3=Wl if BS)
        int ci   = idx & 511;
        int row  = ci >> 2, ch = ci & 3;
        const __half* src =
            (bsel == 0) ? Ah + (long)(m0 + row) * 1024 + kc + ch * 8 :
            (bsel == 1) ? Al + (long)(m0 + row) * 1024 + kc + ch * 8 :
            (bsel == 2) ? Wh + (long)(n0 + row) * 1024 + kc + ch * 8 :
                          Wl + (long)(n0 + row) * 1024 + kc + ch * 8;
        uint32_t dst = stb + (uint32_t)(bsel * 8192) + (uint32_t)(row * 64)
                     + (uint32_t)(((ch ^ ((row >> 1) & 3)) << 4));
        cpa(dst, src);
    }
}

template<int MODE, int BS>
__device__ __forceinline__ void gemm_async(
    const __half* __restrict__ Ah, const __half* __restrict__ Al,
    const __half* __restrict__ Wh, const __half* __restrict__ Wl,
    const float* __restrict__ bias, float oscale,
    float* __restrict__ Cf,
    __half* __restrict__ Oh, __half* __restrict__ Ol,
    float* __restrict__ Of,
    char* smem)
{
    const int tid = threadIdx.x;
    const int wid = tid >> 5;
    const int l   = tid & 31;
    const int m0  = blockIdx.y * 128;
    const int n0  = blockIdx.x * 128;
    const int wm  = (wid / 4) * 64;
    const int wn  = (wid % 4) * 32;

    const int aRow = (l & 15);
    const int aCk  = (l >> 4);
    const int bRow = ((l >> 4) & 1) * 8 + (l & 7);
    const int bCk  = (l >> 3) & 1;
    const uint32_t STGB = BS ? 32768u : 24576u;

    float acc[4][4][4];
    #pragma unroll
    for (int a = 0; a < 4; ++a)
        #pragma unroll
        for (int b = 0; b < 4; ++b)
            #pragma unroll
            for (int c = 0; c < 4; ++c) acc[a][b][c] = 0.0f;

    const uint32_t sb = smem_u32(smem);

    gemm_issue<BS>(Ah, Al, Wh, Wl, m0, n0, 0, sb, tid); CP_COMMIT();
    gemm_issue<BS>(Ah, Al, Wh, Wl, m0, n0, 1, sb, tid); CP_COMMIT();

    for (int c = 0; c < 32; ++c) {
        if (c < 31) { CP_WAIT(1); } else { CP_WAIT(0); }
        __syncthreads();
        if (c + 2 < 32) {
            gemm_issue<BS>(Ah, Al, Wh, Wl, m0, n0, c + 2, sb, tid);
            CP_COMMIT();
        }

        const uint32_t stb = sb + (uint32_t)(c % 3) * STGB;
        const uint32_t ahi = stb;
        const uint32_t alo = stb + 8192;
        const uint32_t bhi = stb + 16384;
        const uint32_t blo = stb + 24576;    // only valid when BS=1

        #pragma unroll
        for (int ks = 0; ks < 2; ++ks) {
            uint32_t ah[4][4], al[4][4], bh[2][4], bl[2][4];
            #pragma unroll
            for (int mt = 0; mt < 4; ++mt) {
                int row = wm + mt * 16 + aRow;
                uint32_t off = (uint32_t)(row * 64)
                             + (uint32_t)((((2*ks + aCk) ^ ((row >> 1) & 3)) << 4));
                ldm_x4(ah[mt], ahi + off);
                ldm_x4(al[mt], alo + off);
            }
            #pragma unroll
            for (int nb = 0; nb < 2; ++nb) {
                int row = wn + nb * 16 + bRow;
                uint32_t off = (uint32_t)(row * 64)
                             + (uint32_t)((((2*ks + bCk) ^ ((row >> 1) & 3)) << 4));
                ldm_x4(bh[nb], bhi + off);
                if (BS) ldm_x4(bl[nb], blo + off);
            }
            // pass 1: ah x bh
            #pragma unroll
            for (int mt = 0; mt < 4; ++mt)
                #pragma unroll
                for (int nt = 0; nt < 4; ++nt) {
                    const uint32_t* pb = &bh[nt >> 1][(nt & 1) * 2];
                    mma16816(acc[mt][nt], ah[mt], pb[0], pb[1]);
                }
            // pass 2 (BS only): ah x bl
            if (BS) {
                #pragma unroll
                for (int mt = 0; mt < 4; ++mt)
                    #pragma unroll
                    for (int nt = 0; nt < 4; ++nt) {
                        const uint32_t* pb = &bl[nt >> 1][(nt & 1) * 2];
                        mma16816(acc[mt][nt], ah[mt], pb[0], pb[1]);
                    }
            }
            // pass 3: al x bh
            #pragma unroll
            for (int mt = 0; mt < 4; ++mt)
                #pragma unroll
                for (int nt = 0; nt < 4; ++nt) {
                    const uint32_t* pb = &bh[nt >> 1][(nt & 1) * 2];
                    mma16816(acc[mt][nt], al[mt], pb[0], pb[1]);
                }
        }
    }

    #pragma unroll
    for (int mt = 0; mt < 4; ++mt) {
        #pragma unroll
        for (int nt = 0; nt < 4; ++nt) {
            int n = n0 + wn + nt * 8 + (l & 3) * 2;
            float2 bb = *(const float2*)(bias + n);
            #pragma unroll
            for (int half = 0; half < 2; ++half) {
                int m = m0 + wm + mt * 16 + (l >> 2) + half * 8;
                float2 r;
                r.x = (acc[mt][nt][half*2]   + bb.x) * oscale;
                r.y = (acc[mt][nt][half*2+1] + bb.y) * oscale;
                if (MODE == 0) {
                    *(float2*)(Cf + (long)m * 1024 + n) = r;
                } else {
                    int b2 = m >> 11, s = m & 2047;
                    int h = n >> 6, hd = n & 63;
                    long addr = ((long)(b2 * H_ + h) * S_ + s) * HD_ + hd;
                    uint32_t hv = packh(r.x, r.y);
                    *(uint32_t*)(Oh + addr) = hv;
                    if (Ol) *(uint32_t*)(Ol + addr) = packh_lo(r.x, r.y, hv);
                    if (Of) *(float2*)(Of + addr) = r;
                }
            }
        }
    }
}

// K projection: 3-MMA (K stays split downstream)
__global__ void __launch_bounds__(256, 2)
gemm_k(const __half* __restrict__ xh, const __half* __restrict__ xl,
       const __half* __restrict__ wh, const __half* __restrict__ wl,
       const float* __restrict__ bk,
       __half* __restrict__ kh, __half* __restrict__ kl)
{
    extern __shared__ char smem[];
    gemm_async<1, 1>(xh, xl, wh + (1L << 20), wl + (1L << 20),
                     bk, 1.0f, nullptr, kh, kl, nullptr, smem);
}

// Q and V projections: 2-MMA (outputs consumed as fp16-single downstream)
// Q pre-scaled by SSCALE (softmax scale folded in).
__global__ void __launch_bounds__(256, 2)
gemm_qv(const __half* __restrict__ xh, const __half* __restrict__ xl,
        const __half* __restrict__ wh,
        const float* __restrict__ bq, const float* __restrict__ bv,
        __half* __restrict__ qh, __half* __restrict__ vh,
        float* __restrict__ vf)
{
    extern __shared__ char smem[];
    const int z = blockIdx.z;                 // 0=Q, else V
    const __half* Wh = wh + ((long)(z == 0 ? 0 : 2) << 20);
    const float* bias = (z == 0) ? bq : bv;
    float oscale = (z == 0) ? SSCALE : 1.0f;
    __half* Oh = (z == 0) ? qh : vh;
    float* Of = (z == 0) ? nullptr : vf;
    gemm_async<1, 0>(xh, xl, Wh, nullptr, bias, oscale, nullptr, Oh, nullptr, Of, smem);
}

__global__ void __launch_bounds__(256, 2)
gemm_out(const __half* __restrict__ ah, const __half* __restrict__ al,
         const __half* __restrict__ wh,
         const float* __restrict__ bias, float* __restrict__ C)
{
    extern __shared__ char smem[];
    gemm_async<0, 0>(ah, al, wh + ((long)3 << 20), nullptr,
                     bias, 1.0f, C, nullptr, nullptr, nullptr, smem);
}

// ============================================================================
// Fused attention, 2 CTAs/SM: KV block 64 rows, 32 iterations.
// smem: Q 16K (single, pre-scaled) | K 2x16K (hi+lo) | V 2x8K = 64 KB.
// QK^T: 2-MMA (Q single, K split). PV: 1-MMA (P single, V single).
// ============================================================================
__device__ __forceinline__ void issue_q(const __half* __restrict__ Gh,
    uint32_t dst, int tid)
{
    #pragma unroll
    for (int it = 0; it < 4; ++it) {
        int idx = tid + it * 256;
        int row = idx >> 3, ch = idx & 7;
        uint32_t off = (uint32_t)(row * 128) + (uint32_t)(((ch ^ (row & 7)) << 4));
        cpa(dst + off, Gh + row * 64 + ch * 8);
    }
}
__device__ __forceinline__ void issue_k64(const __half* __restrict__ Gh,
    const __half* __restrict__ Gl, uint32_t dst_hi, int tid)
{
    #pragma unroll
    for (int it = 0; it < 2; ++it) {
        int idx = tid + it * 256;       // 0..511
        int row = idx >> 3, ch = idx & 7;
        uint32_t off = (uint32_t)(row * 128) + (uint32_t)(((ch ^ (row & 7)) << 4));
        cpa(dst_hi + off,        Gh + row * 64 + ch * 8);
        cpa(dst_hi + 8192 + off, Gl + row * 64 + ch * 8);
    }
}
__device__ __forceinline__ void issue_v64(const __half* __restrict__ Gh,
    uint32_t dst, int tid)
{
    #pragma unroll
    for (int it = 0; it < 2; ++it) {
        int idx = tid + it * 256;       // 0..511
        int row = idx >> 3, ch = idx & 7;
        uint32_t off = (uint32_t)(row * 128) + (uint32_t)(((ch ^ (row & 7)) << 4));
        cpa(dst + off, Gh + row * 64 + ch * 8);
    }
}

__global__ void __launch_bounds__(256, 2)
fused_attn(const __half* __restrict__ Qh,
           const __half* __restrict__ Kh, const __half* __restrict__ Kl,
           const __half* __restrict__ Vh, const float* __restrict__ VF,
           __half* __restrict__ OBh, __half* __restrict__ OBl)
{
    extern __shared__ char sm[];
    const int tid = threadIdx.x;
    const int wid = tid >> 5;
    const int l   = tid & 31;
    const int g   = blockIdx.y;
    const int m0  = blockIdx.x * 128;
    const int wm  = wid * 16;

    const long gbase = (long)g * S_ * HD_;
    const __half* Kgh = Kh + gbase;
    const __half* Kgl = Kl + gbase;
    const __half* Vgh = Vh + gbase;

    const uint32_t sb = smem_u32(sm);
    const uint32_t qb = sb;                 // Q single plane, 16K
    // K buffers @16384 + cur*16384 (hi, lo@+8192); V @49152 + cur*8192

    // prologue: Q + K0 + V0 as group 0
    issue_q(Qh + gbase + (long)m0 * HD_, sb, tid);
    issue_k64(Kgh, Kgl, sb + 16384, tid);
    issue_v64(Vgh, sb + 49152, tid);
    CP_COMMIT();

    float oacc[8][4];
    #pragma unroll
    for (int i = 0; i < 8; ++i)
        #pragma unroll
        for (int j = 0; j < 4; ++j) oacc[i][j] = 0.0f;
    float mrun[2] = {-1e30f, -1e30f};   // log2 domain (scores pre-scaled)
    float lsum[2] = {0.0f, 0.0f};

    const int aR = wm + (l & 15);
    const int bR = ((l >> 4) & 1) * 8 + (l & 7);
    const int bC = (l >> 3) & 1;
    const int vR = (l & 15);
    const int vC = (l >> 4);

    for (int j = 0; j < 32; ++j) {
        const int cur = j & 1;
        const uint32_t kb = sb + 16384 + cur * 16384;
        const uint32_t vb = sb + 49152 + cur * 8192;

        __syncthreads();   // buffer (j+1)&1 free (consumed in iter j-1)
        if (j + 1 < 32) {
            const int nxt = cur ^ 1;
            issue_k64(Kgh + (long)(j + 1) * 4096, Kgl + (long)(j + 1) * 4096,
                      sb + 16384 + nxt * 16384, tid);
            issue_v64(Vgh + (long)(j + 1) * 4096, sb + 49152 + nxt * 8192, tid);
            CP_COMMIT();
        }
        if (j < 31) { CP_WAIT(1); } else { CP_WAIT(0); }
        __syncthreads();

        // ---- S = Q K^T : warp tile 16 x 64, 2-MMA (Q single, K split) ----
        float sacc[8][4];
        #pragma unroll
        for (int i = 0; i < 8; ++i)
            #pragma unroll
            for (int c = 0; c < 4; ++c) sacc[i][c] = 0.0f;

        #pragma unroll
        for (int ks = 0; ks < 4; ++ks) {
            uint32_t ah[4];
            {
                uint32_t off = (uint32_t)(aR * 128)
                             + (uint32_t)((((ks * 2 + (l >> 4)) ^ (aR & 7)) << 4));
                ldm_x4(ah, qb + off);
            }
            #pragma unroll
            for (int nbp = 0; nbp < 4; nbp += 2) {
                uint32_t bh[2][4], bl[2][4];
                #pragma unroll
                for (int i = 0; i < 2; ++i) {
                    int row = (nbp + i) * 16 + bR;
                    uint32_t off = (uint32_t)(row * 128)
                                 + (uint32_t)((((ks * 2 + bC) ^ (row & 7)) << 4));
                    ldm_x4(bh[i], kb + off);
                    ldm_x4(bl[i], kb + 8192 + off);
                }
                // pass 1: q x kh
                #pragma unroll
                for (int i = 0; i < 2; ++i)
                    #pragma unroll
                    for (int nt2 = 0; nt2 < 2; ++nt2)
                        mma16816(sacc[(nbp + i) * 2 + nt2], ah,
                                 bh[i][nt2*2], bh[i][nt2*2+1]);
                // pass 2: q x kl
                #pragma unroll
                for (int i = 0; i < 2; ++i)
                    #pragma unroll
                    for (int nt2 = 0; nt2 < 2; ++nt2)
                        mma16816(sacc[(nbp + i) * 2 + nt2], ah,
                                 bl[i][nt2*2], bl[i][nt2*2+1]);
            }
        }

        // ---- online softmax (log2 domain, scores pre-scaled) ----
        float mnew[2] = {-1e30f, -1e30f};
        #pragma unroll
        for (int nt = 0; nt < 8; ++nt) {
            mnew[0] = fmaxf(mnew[0], fmaxf(sacc[nt][0], sacc[nt][1]));
            mnew[1] = fmaxf(mnew[1], fmaxf(sacc[nt][2], sacc[nt][3]));
        }
        #pragma unroll
        for (int h = 0; h < 2; ++h) {
            mnew[h] = fmaxf(mnew[h], __shfl_xor_sync(0xffffffffu, mnew[h], 1));
            mnew[h] = fmaxf(mnew[h], __shfl_xor_sync(0xffffffffu, mnew[h], 2));
        }
        float corr[2];
        #pragma unroll
        for (int h = 0; h < 2; ++h) {
            float mi = fmaxf(mrun[h], mnew[h]);
            corr[h] = fexp2(mrun[h] - mi);
            mrun[h] = mi;
            lsum[h] *= corr[h];
        }
        float rs[2] = {0.0f, 0.0f};
        #pragma unroll
        for (int nt = 0; nt < 8; ++nt) {
            sacc[nt][0] = fexp2(sacc[nt][0] - mrun[0]);
            sacc[nt][1] = fexp2(sacc[nt][1] - mrun[0]);
            sacc[nt][2] = fexp2(sacc[nt][2] - mrun[1]);
            sacc[nt][3] = fexp2(sacc[nt][3] - mrun[1]);
            rs[0] += sacc[nt][0] + sacc[nt][1];
            rs[1] += sacc[nt][2] + sacc[nt][3];
        }
        #pragma unroll
        for (int h = 0; h < 2; ++h) {
            rs[h] += __shfl_xor_sync(0xffffffffu, rs[h], 1);
            rs[h] += __shfl_xor_sync(0xffffffffu, rs[h], 2);
            lsum[h] += rs[h];
        }
        #pragma unroll
        for (int nt = 0; nt < 8; ++nt) {
            oacc[nt][0] *= corr[0]; oacc[nt][1] *= corr[0];
            oacc[nt][2] *= corr[1]; oacc[nt][3] *= corr[1];
        }

        // ---- O += P V : 1-MMA (P single, V single) ----
        #pragma unroll
        for (int kt = 0; kt < 4; ++kt) {
            uint32_t ph[4];
            ph[0] = packh(sacc[2*kt][0],   sacc[2*kt][1]);
            ph[1] = packh(sacc[2*kt][2],   sacc[2*kt][3]);
            ph[2] = packh(sacc[2*kt+1][0], sacc[2*kt+1][1]);
            ph[3] = packh(sacc[2*kt+1][2], sacc[2*kt+1][3]);
            #pragma unroll
            for (int npp = 0; npp < 4; npp += 2) {
                uint32_t vh[2][4];
                #pragma unroll
                for (int i = 0; i < 2; ++i) {
                    int row = kt * 16 + vR;
                    uint32_t off = (uint32_t)(row * 128)
                                 + (uint32_t)(((((npp + i) * 2 + vC) ^ (row & 7)) << 4));
                    ldm_x4_t(vh[i], vb + off);
                }
                #pragma unroll
                for (int i = 0; i < 2; ++i)
                    #pragma unroll
                    for (int d2 = 0; d2 < 2; ++d2)
                        mma16816(oacc[(npp + i) * 2 + d2], ph,
                                 vh[i][d2*2], vh[i][d2*2+1]);
            }
        }
    }

    // ---- finalize: 1/l, Gram-Schmidt exclusion, fp16 hi/lo store [b,s,d] ----
    float inv[2] = {1.0f / lsum[0], 1.0f / lsum[1]};
    #pragma unroll
    for (int nt = 0; nt < 8; ++nt) {
        oacc[nt][0] *= inv[0]; oacc[nt][1] *= inv[0];
        oacc[nt][2] *= inv[1]; oacc[nt][3] *= inv[1];
    }

    const int bb = g >> 4, hh = g & 15;
    #pragma unroll
    for (int half = 0; half < 2; ++half) {
        int grow = m0 + wm + (l >> 2) + half * 8;
        const float* vr = VF + gbase + (long)grow * HD_;
        float vv[16];
        float dov = 0.0f, dvv = 0.0f;
        #pragma unroll
        for (int nt = 0; nt < 8; ++nt) {
            float2 t = *(const float2*)(vr + nt * 8 + (l & 3) * 2);
            vv[2*nt] = t.x; vv[2*nt+1] = t.y;
            float o0 = oacc[nt][half*2], o1 = oacc[nt][half*2+1];
            dov += o0 * t.x + o1 * t.y;
            dvv += t.x * t.x + t.y * t.y;
        }
        dov += __shfl_xor_sync(0xffffffffu, dov, 1);
        dov += __shfl_xor_sync(0xffffffffu, dov, 2);
        dvv += __shfl_xor_sync(0xffffffffu, dvv, 1);
        dvv += __shfl_xor_sync(0xffffffffu, dvv, 2);
        float al_ = dov / (dvv + 1e-8f);
        long obase = (long)(bb * S_ + grow) * D_ + hh * HD_;
        #pragma unroll
        for (int nt = 0; nt < 8; ++nt) {
            float rx = oacc[nt][half*2]   - al_ * vv[2*nt];
            float ry = oacc[nt][half*2+1] - al_ * vv[2*nt+1];
            long a = obase + nt * 8 + (l & 3) * 2;
            uint32_t hv = packh(rx, ry);
            *(uint32_t*)(OBh + a) = hv;
            *(uint32_t*)(OBl + a) = packh_lo(rx, ry, hv);
        }
    }
}

// ============================================================================
extern "C" void kernel_launch(void* const* d_in, const int* in_sizes, int n_in,
                              void* d_out, int out_size)
{
    const float* x  = (const float*)d_in[0];
    const float* wq = (const float*)d_in[1];
    const float* bq = (const float*)d_in[2];
    const float* wk = (const float*)d_in[3];
    const float* bk = (const float*)d_in[4];
    const float* wv = (const float*)d_in[5];
    const float* bv = (const float*)d_in[6];
    const float* wo = (const float*)d_in[7];
    const float* bo = (const float*)d_in[8];
    float* out = (float*)d_out;

    __half *xh, *xl, *wh, *wl, *qh, *kh, *kl, *vh, *obh, *obl;
    float *vf;
    cudaGetSymbolAddress((void**)&xh,  g_xh);
    cudaGetSymbolAddress((void**)&xl,  g_xl);
    cudaGetSymbolAddress((void**)&wh,  g_wh);
    cudaGetSymbolAddress((void**)&wl,  g_wl);
    cudaGetSymbolAddress((void**)&qh,  g_qh);
    cudaGetSymbolAddress((void**)&kh,  g_kh);
    cudaGetSymbolAddress((void**)&kl,  g_kl);
    cudaGetSymbolAddress((void**)&vh,  g_vh);
    cudaGetSymbolAddress((void**)&vf,  g_vf);
    cudaGetSymbolAddress((void**)&obh, g_obh);
    cudaGetSymbolAddress((void**)&obl, g_obl);

    const int SMG1 = 3 * 32768;    // 98304  (K proj, B split)
    const int SMG0 = 3 * 24576;    // 73728  (Q/V proj + out, B single)
    const int SMF  = 65536;        // Q 16K + K 32K + V 16K
    cudaFuncSetAttribute(gemm_k,   cudaFuncAttributeMaxDynamicSharedMemorySize, SMG1);
    cudaFuncSetAttribute(gemm_qv,  cudaFuncAttributeMaxDynamicSharedMemorySize, SMG0);
    cudaFuncSetAttribute(gemm_out, cudaFuncAttributeMaxDynamicSharedMemorySize, SMG0);
    cudaFuncSetAttribute(fused_attn, cudaFuncAttributeMaxDynamicSharedMemorySize, SMF);

    // 0) convert x + weights to fp16 hi/lo
    convert_all<<<dim3(512, 8), 256>>>(x, wq, wk, wv, wo, xh, xl, wh, wl);

    // 1) projections: K (3-MMA, split out), Q+V (2-MMA, single out; Q pre-scaled)
    gemm_k <<<dim3(D_/128, M_/128, 1), 256, SMG1>>>(xh, xl, wh, wl, bk, kh, kl);
    gemm_qv<<<dim3(D_/128, M_/128, 2), 256, SMG0>>>(xh, xl, wh, bq, bv, qh, vh, vf);

    // 2) fused attention + softmax + exclusion -> ob fp16 hi/lo [b,s,d]
    fused_attn<<<dim3(S_/128, G_), 256, SMF>>>(qh, kh, kl, vh, vf, obh, obl);

    // 3) output projection (2-MMA, Wo single) -> d_out
    gemm_out<<<dim3(D_/128, M_/128, 1), 256, SMG0>>>(obh, obl, wh, bo, out);
}

// round 16
// speedup vs baseline: 2.4452x; 1.1106x over previous
#include <cuda_runtime.h>
#include <cuda_fp16.h>
#include <cstdint>

#define B_   2
#define S_   2048
#define D_   1024
#define H_   16
#define HD_  64
#define M_   (B_*S_)     // 4096
#define G_   (B_*H_)     // 32
#define NE_  ((size_t)M_*D_)   // 4194304

// ---- scratch (static device arrays; no allocation allowed) ----
__device__ __half g_xh[NE_], g_xl[NE_];      // x fp16 hi/lo
__device__ __half g_wh[NE_], g_wl[NE_];      // wq|wk|wv|wo hi/lo
__device__ __half g_qh[NE_];                 // Q head layout (single, pre-scaled)
__device__ __half g_kh[NE_], g_kl[NE_];      // K split
__device__ __half g_vh[NE_];                 // V fp16 (single plane)
__device__ float  g_vf[NE_];                 // V fp32 (exclusion)
__device__ __half g_obh[NE_];                // attn out [b,s,d] (single plane)

// ============================================================================
// helpers
// ============================================================================
__device__ __forceinline__ uint32_t smem_u32(const void* p) {
    uint32_t a;
    asm("{ .reg .u64 t; cvta.to.shared.u64 t, %1; cvt.u32.u64 %0, t; }"
        : "=r"(a) : "l"(p));
    return a;
}
__device__ __forceinline__ void ldm_x4(uint32_t* r, uint32_t addr) {
    asm volatile("ldmatrix.sync.aligned.m8n8.x4.shared.b16 {%0,%1,%2,%3}, [%4];"
        : "=r"(r[0]), "=r"(r[1]), "=r"(r[2]), "=r"(r[3]) : "r"(addr));
}
__device__ __forceinline__ void ldm_x4_t(uint32_t* r, uint32_t addr) {
    asm volatile("ldmatrix.sync.aligned.m8n8.x4.trans.shared.b16 {%0,%1,%2,%3}, [%4];"
        : "=r"(r[0]), "=r"(r[1]), "=r"(r[2]), "=r"(r[3]) : "r"(addr));
}
__device__ __forceinline__ void mma16816(float* c, const uint32_t* a,
                                         uint32_t b0, uint32_t b1) {
    asm volatile(
        "mma.sync.aligned.m16n8k16.row.col.f32.f16.f16.f32 "
        "{%0,%1,%2,%3}, {%4,%5,%6,%7}, {%8,%9}, {%0,%1,%2,%3};"
        : "+f"(c[0]), "+f"(c[1]), "+f"(c[2]), "+f"(c[3])
        : "r"(a[0]), "r"(a[1]), "r"(a[2]), "r"(a[3]), "r"(b0), "r"(b1));
}
__device__ __forceinline__ uint32_t packh(float x, float y) {
    __half2 t = __floats2half2_rn(x, y);
    return *(uint32_t*)&t;
}
__device__ __forceinline__ uint32_t packh_lo(float x, float y, uint32_t hi) {
    __half2 h = *(__half2*)&hi;
    return packh(x - __half2float(h.x), y - __half2float(h.y));
}
__device__ __forceinline__ float fexp2(float x) {
    float y;
    asm("ex2.approx.f32 %0, %1;" : "=f"(y) : "f"(x));
    return y;
}
__device__ __forceinline__ void cpa(uint32_t dst, const void* src) {
    asm volatile("cp.async.cg.shared.global [%0], [%1], 16;"
        :: "r"(dst), "l"(src) : "memory");
}
#define CP_COMMIT() asm volatile("cp.async.commit_group;" ::: "memory")
#define CP_WAIT(n)  asm volatile("cp.async.wait_group %0;" :: "n"(n) : "memory")

// 0.125 (1/sqrt(64)) * log2(e)  -> softmax run in log2 domain (folded into Q)
#define SSCALE 0.18033688f

// ============================================================================
// Convert pass: x (4 quarters) + 4 weights -> fp16 hi/lo
// ============================================================================
__global__ void __launch_bounds__(256)
convert_all(const float* __restrict__ x,
            const float* __restrict__ wq, const float* __restrict__ wk,
            const float* __restrict__ wv, const float* __restrict__ wo,
            __half* __restrict__ xh, __half* __restrict__ xl,
            __half* __restrict__ wh, __half* __restrict__ wl)
{
    const int z = blockIdx.y;
    const float* src;
    __half *dh, *dl;
    if (z < 4) {
        src = x  + ((long)z << 20);
        dh  = xh + ((long)z << 20);
        dl  = xl + ((long)z << 20);
    } else {
        const float* ws = (z == 4) ? wq : (z == 5) ? wk : (z == 6) ? wv : wo;
        src = ws;
        dh  = wh + ((long)(z - 4) << 20);
        dl  = wl + ((long)(z - 4) << 20);
    }
    long i = ((long)blockIdx.x * 256 + threadIdx.x) * 8;
    float4 a = *(const float4*)(src + i);
    float4 b = *(const float4*)(src + i + 4);
    uint32_t h0 = packh(a.x, a.y), h1 = packh(a.z, a.w);
    uint32_t h2 = packh(b.x, b.y), h3 = packh(b.z, b.w);
    uint32_t l0 = packh_lo(a.x, a.y, h0), l1 = packh_lo(a.z, a.w, h1);
    uint32_t l2 = packh_lo(b.x, b.y, h2), l3 = packh_lo(b.z, b.w, h3);
    *(uint4*)(dh + i) = make_uint4(h0, h1, h2, h3);
    *(uint4*)(dl + i) = make_uint4(l0, l1, l2, l3);
}

// ============================================================================
// fp16 cp.async GEMM: C = oscale*(A W^T + bias). BM=BN=128, BK=32, 3-stage.
// AS: A split (adds al x bh pass), BS: B split (adds ah x bl pass).
// Stage = (2+AS+BS)*8K. Planes in smem: [Ah, (Al), Wh, (Wl)].
// ============================================================================
template<int AS, int BS>
__device__ __forceinline__ void gemm_issue(
    const __half* __restrict__ Ah, const __half* __restrict__ Al,
    const __half* __restrict__ Wh, const __half* __restrict__ Wl,
    int m0, int n0, int s, uint32_t sb, int tid)
{
    const int kc = s * 32;
    constexpr int P = 2 + AS + BS;
    const uint32_t stb = sb + (uint32_t)(s % 3) * (P * 8192u);
    #pragma unroll
    for (int it = 0; it < P * 2; ++it) {
        int idx = tid + it * 256;
        int p   = idx >> 9;
        int ci  = idx & 511;
        int row = ci >> 2, ch = ci & 3;
        const __half* src;
        if (p == 0)                 src = Ah + (long)(m0 + row) * 1024 + kc + ch * 8;
        else if (AS && p == 1)      src = Al + (long)(m0 + row) * 1024 + kc + ch * 8;
        else if (p == 1 + AS)       src = Wh + (long)(n0 + row) * 1024 + kc + ch * 8;
        else                        src = Wl + (long)(n0 + row) * 1024 + kc + ch * 8;
        uint32_t dst = stb + (uint32_t)(p * 8192) + (uint32_t)(row * 64)
                     + (uint32_t)(((ch ^ ((row >> 1) & 3)) << 4));
        cpa(dst, src);
    }
}

template<int MODE, int AS, int BS>
__device__ __forceinline__ void gemm_async(
    const __half* __restrict__ Ah, const __half* __restrict__ Al,
    const __half* __restrict__ Wh, const __half* __restrict__ Wl,
    const float* __restrict__ bias, float oscale,
    float* __restrict__ Cf,
    __half* __restrict__ Oh, __half* __restrict__ Ol,
    float* __restrict__ Of,
    char* smem)
{
    const int tid = threadIdx.x;
    const int wid = tid >> 5;
    const int l   = tid & 31;
    const int m0  = blockIdx.y * 128;
    const int n0  = blockIdx.x * 128;
    const int wm  = (wid / 4) * 64;
    const int wn  = (wid % 4) * 32;

    const int aRow = (l & 15);
    const int aCk  = (l >> 4);
    const int bRow = ((l >> 4) & 1) * 8 + (l & 7);
    const int bCk  = (l >> 3) & 1;
    constexpr int P = 2 + AS + BS;
    const uint32_t STGB = P * 8192u;

    float acc[4][4][4];
    #pragma unroll
    for (int a = 0; a < 4; ++a)
        #pragma unroll
        for (int b = 0; b < 4; ++b)
            #pragma unroll
            for (int c = 0; c < 4; ++c) acc[a][b][c] = 0.0f;

    const uint32_t sb = smem_u32(smem);

    gemm_issue<AS, BS>(Ah, Al, Wh, Wl, m0, n0, 0, sb, tid); CP_COMMIT();
    gemm_issue<AS, BS>(Ah, Al, Wh, Wl, m0, n0, 1, sb, tid); CP_COMMIT();

    for (int c = 0; c < 32; ++c) {
        if (c < 31) { CP_WAIT(1); } else { CP_WAIT(0); }
        __syncthreads();
        if (c + 2 < 32) {
            gemm_issue<AS, BS>(Ah, Al, Wh, Wl, m0, n0, c + 2, sb, tid);
            CP_COMMIT();
        }

        const uint32_t stb = sb + (uint32_t)(c % 3) * STGB;
        const uint32_t ahi = stb;
        const uint32_t alo = stb + 8192;                 // valid if AS
        const uint32_t bhi = stb + (1 + AS) * 8192;
        const uint32_t blo = bhi + 8192;                 // valid if BS

        #pragma unroll
        for (int ks = 0; ks < 2; ++ks) {
            uint32_t ah[4][4], al[4][4], bh[2][4], bl[2][4];
            #pragma unroll
            for (int mt = 0; mt < 4; ++mt) {
                int row = wm + mt * 16 + aRow;
                uint32_t off = (uint32_t)(row * 64)
                             + (uint32_t)((((2*ks + aCk) ^ ((row >> 1) & 3)) << 4));
                ldm_x4(ah[mt], ahi + off);
                if (AS) ldm_x4(al[mt], alo + off);
            }
            #pragma unroll
            for (int nb = 0; nb < 2; ++nb) {
                int row = wn + nb * 16 + bRow;
                uint32_t off = (uint32_t)(row * 64)
                             + (uint32_t)((((2*ks + bCk) ^ ((row >> 1) & 3)) << 4));
                ldm_x4(bh[nb], bhi + off);
                if (BS) ldm_x4(bl[nb], blo + off);
            }
            // pass 1: ah x bh
            #pragma unroll
            for (int mt = 0; mt < 4; ++mt)
                #pragma unroll
                for (int nt = 0; nt < 4; ++nt) {
                    const uint32_t* pb = &bh[nt >> 1][(nt & 1) * 2];
                    mma16816(acc[mt][nt], ah[mt], pb[0], pb[1]);
                }
            // pass 2 (BS): ah x bl
            if (BS) {
                #pragma unroll
                for (int mt = 0; mt < 4; ++mt)
                    #pragma unroll
                    for (int nt = 0; nt < 4; ++nt) {
                        const uint32_t* pb = &bl[nt >> 1][(nt & 1) * 2];
                        mma16816(acc[mt][nt], ah[mt], pb[0], pb[1]);
                    }
            }
            // pass 3 (AS): al x bh
            if (AS) {
                #pragma unroll
                for (int mt = 0; mt < 4; ++mt)
                    #pragma unroll
                    for (int nt = 0; nt < 4; ++nt) {
                        const uint32_t* pb = &bh[nt >> 1][(nt & 1) * 2];
                        mma16816(acc[mt][nt], al[mt], pb[0], pb[1]);
                    }
            }
        }
    }

    #pragma unroll
    for (int mt = 0; mt < 4; ++mt) {
        #pragma unroll
        for (int nt = 0; nt < 4; ++nt) {
            int n = n0 + wn + nt * 8 + (l & 3) * 2;
            float2 bb = *(const float2*)(bias + n);
            #pragma unroll
            for (int half = 0; half < 2; ++half) {
                int m = m0 + wm + mt * 16 + (l >> 2) + half * 8;
                float2 r;
                r.x = (acc[mt][nt][half*2]   + bb.x) * oscale;
                r.y = (acc[mt][nt][half*2+1] + bb.y) * oscale;
                if (MODE == 0) {
                    *(float2*)(Cf + (long)m * 1024 + n) = r;
                } else {
                    int b2 = m >> 11, s = m & 2047;
                    int h = n >> 6, hd = n & 63;
                    long addr = ((long)(b2 * H_ + h) * S_ + s) * HD_ + hd;
                    uint32_t hv = packh(r.x, r.y);
                    *(uint32_t*)(Oh + addr) = hv;
                    if (Ol) *(uint32_t*)(Ol + addr) = packh_lo(r.x, r.y, hv);
                    if (Of) *(float2*)(Of + addr) = r;
                }
            }
        }
    }
}

// K projection: 3-MMA (A split, B split)
__global__ void __launch_bounds__(256, 2)
gemm_k(const __half* __restrict__ xh, const __half* __restrict__ xl,
       const __half* __restrict__ wh, const __half* __restrict__ wl,
       const float* __restrict__ bk,
       __half* __restrict__ kh, __half* __restrict__ kl)
{
    extern __shared__ char smem[];
    gemm_async<1, 1, 1>(xh, xl, wh + (1L << 20), wl + (1L << 20),
                        bk, 1.0f, nullptr, kh, kl, nullptr, smem);
}

// Q projection: 2-MMA (A split, B single); pre-scaled by SSCALE
__global__ void __launch_bounds__(256, 2)
gemm_q(const __half* __restrict__ xh, const __half* __restrict__ xl,
       const __half* __restrict__ wh, const float* __restrict__ bq,
       __half* __restrict__ qh)
{
    extern __shared__ char smem[];
    gemm_async<1, 1, 0>(xh, xl, wh, nullptr,
                        bq, SSCALE, nullptr, qh, nullptr, nullptr, smem);
}

// V projection: 1-MMA (A single, B single)
__global__ void __launch_bounds__(256, 2)
gemm_v(const __half* __restrict__ xh,
       const __half* __restrict__ wh, const float* __restrict__ bv,
       __half* __restrict__ vh, float* __restrict__ vf)
{
    extern __shared__ char smem[];
    gemm_async<1, 0, 0>(xh, nullptr, wh + (2L << 20), nullptr,
                        bv, 1.0f, nullptr, vh, nullptr, vf, smem);
}

// Output projection: 1-MMA (A single, B single)
__global__ void __launch_bounds__(256, 2)
gemm_out(const __half* __restrict__ ah,
         const __half* __restrict__ wh,
         const float* __restrict__ bias, float* __restrict__ C)
{
    extern __shared__ char smem[];
    gemm_async<0, 0, 0>(ah, nullptr, wh + ((long)3 << 20), nullptr,
                        bias, 1.0f, C, nullptr, nullptr, nullptr, smem);
}

// ============================================================================
// Fused attention, 2 CTAs/SM: KV block 64 rows, 32 iterations.
// smem: Q 16K (single, pre-scaled) | K 2x16K (hi+lo) | V 2x8K = 64 KB.
// QK^T: 2-MMA (Q single, K split). PV: 1-MMA. Output: fp16 single plane.
// ============================================================================
__device__ __forceinline__ void issue_q(const __half* __restrict__ Gh,
    uint32_t dst, int tid)
{
    #pragma unroll
    for (int it = 0; it < 4; ++it) {
        int idx = tid + it * 256;
        int row = idx >> 3, ch = idx & 7;
        uint32_t off = (uint32_t)(row * 128) + (uint32_t)(((ch ^ (row & 7)) << 4));
        cpa(dst + off, Gh + row * 64 + ch * 8);
    }
}
__device__ __forceinline__ void issue_k64(const __half* __restrict__ Gh,
    const __half* __restrict__ Gl, uint32_t dst_hi, int tid)
{
    #pragma unroll
    for (int it = 0; it < 2; ++it) {
        int idx = tid + it * 256;       // 0..511
        int row = idx >> 3, ch = idx & 7;
        uint32_t off = (uint32_t)(row * 128) + (uint32_t)(((ch ^ (row & 7)) << 4));
        cpa(dst_hi + off,        Gh + row * 64 + ch * 8);
        cpa(dst_hi + 8192 + off, Gl + row * 64 + ch * 8);
    }
}
__device__ __forceinline__ void issue_v64(const __half* __restrict__ Gh,
    uint32_t dst, int tid)
{
    #pragma unroll
    for (int it = 0; it < 2; ++it) {
        int idx = tid + it * 256;       // 0..511
        int row = idx >> 3, ch = idx & 7;
        uint32_t off = (uint32_t)(row * 128) + (uint32_t)(((ch ^ (row & 7)) << 4));
        cpa(dst + off, Gh + row * 64 + ch * 8);
    }
}

__global__ void __launch_bounds__(256, 2)
fused_attn(const __half* __restrict__ Qh,
           const __half* __restrict__ Kh, const __half* __restrict__ Kl,
           const __half* __restrict__ Vh, const float* __restrict__ VF,
           __half* __restrict__ OBh)
{
    extern __shared__ char sm[];
    const int tid = threadIdx.x;
    const int wid = tid >> 5;
    const int l   = tid & 31;
    const int g   = blockIdx.y;
    const int m0  = blockIdx.x * 128;
    const int wm  = wid * 16;

    const long gbase = (long)g * S_ * HD_;
    const __half* Kgh = Kh + gbase;
    const __half* Kgl = Kl + gbase;
    const __half* Vgh = Vh + gbase;

    const uint32_t sb = smem_u32(sm);
    const uint32_t qb = sb;                 // Q single plane, 16K
    // K buffers @16384 + cur*16384 (hi, lo@+8192); V @49152 + cur*8192

    // prologue: Q + K0 + V0 as group 0
    issue_q(Qh + gbase + (long)m0 * HD_, sb, tid);
    issue_k64(Kgh, Kgl, sb + 16384, tid);
    issue_v64(Vgh, sb + 49152, tid);
    CP_COMMIT();

    float oacc[8][4];
    #pragma unroll
    for (int i = 0; i < 8; ++i)
        #pragma unroll
        for (int j = 0; j < 4; ++j) oacc[i][j] = 0.0f;
    float mrun[2] = {-1e30f, -1e30f};   // log2 domain (scores pre-scaled)
    float lsum[2] = {0.0f, 0.0f};

    const int aR = wm + (l & 15);
    const int bR = ((l >> 4) & 1) * 8 + (l & 7);
    const int bC = (l >> 3) & 1;
    const int vR = (l & 15);
    const int vC = (l >> 4);

    for (int j = 0; j < 32; ++j) {
        const int cur = j & 1;
        const uint32_t kb = sb + 16384 + cur * 16384;
        const uint32_t vb = sb + 49152 + cur * 8192;

        __syncthreads();   // buffer (j+1)&1 free (consumed in iter j-1)
        if (j + 1 < 32) {
            const int nxt = cur ^ 1;
            issue_k64(Kgh + (long)(j + 1) * 4096, Kgl + (long)(j + 1) * 4096,
                      sb + 16384 + nxt * 16384, tid);
            issue_v64(Vgh + (long)(j + 1) * 4096, sb + 49152 + nxt * 8192, tid);
            CP_COMMIT();
        }
        if (j < 31) { CP_WAIT(1); } else { CP_WAIT(0); }
        __syncthreads();

        // ---- S = Q K^T : warp tile 16 x 64, 2-MMA (Q single, K split) ----
        float sacc[8][4];
        #pragma unroll
        for (int i = 0; i < 8; ++i)
            #pragma unroll
            for (int c = 0; c < 4; ++c) sacc[i][c] = 0.0f;

        #pragma unroll
        for (int ks = 0; ks < 4; ++ks) {
            uint32_t ah[4];
            {
                uint32_t off = (uint32_t)(aR * 128)
                             + (uint32_t)((((ks * 2 + (l >> 4)) ^ (aR & 7)) << 4));
                ldm_x4(ah, qb + off);
            }
            #pragma unroll
            for (int nbp = 0; nbp < 4; nbp += 2) {
                uint32_t bh[2][4], bl[2][4];
                #pragma unroll
                for (int i = 0; i < 2; ++i) {
                    int row = (nbp + i) * 16 + bR;
                    uint32_t off = (uint32_t)(row * 128)
                                 + (uint32_t)((((ks * 2 + bC) ^ (row & 7)) << 4));
                    ldm_x4(bh[i], kb + off);
                    ldm_x4(bl[i], kb + 8192 + off);
                }
                // pass 1: q x kh
                #pragma unroll
                for (int i = 0; i < 2; ++i)
                    #pragma unroll
                    for (int nt2 = 0; nt2 < 2; ++nt2)
                        mma16816(sacc[(nbp + i) * 2 + nt2], ah,
                                 bh[i][nt2*2], bh[i][nt2*2+1]);
                // pass 2: q x kl
                #pragma unroll
                for (int i = 0; i < 2; ++i)
                    #pragma unroll
                    for (int nt2 = 0; nt2 < 2; ++nt2)
                        mma16816(sacc[(nbp + i) * 2 + nt2], ah,
                                 bl[i][nt2*2], bl[i][nt2*2+1]);
            }
        }

        // ---- online softmax (log2 domain, scores pre-scaled) ----
        float mnew[2] = {-1e30f, -1e30f};
        #pragma unroll
        for (int nt = 0; nt < 8; ++nt) {
            mnew[0] = fmaxf(mnew[0], fmaxf(sacc[nt][0], sacc[nt][1]));
            mnew[1] = fmaxf(mnew[1], fmaxf(sacc[nt][2], sacc[nt][3]));
        }
        #pragma unroll
        for (int h = 0; h < 2; ++h) {
            mnew[h] = fmaxf(mnew[h], __shfl_xor_sync(0xffffffffu, mnew[h], 1));
            mnew[h] = fmaxf(mnew[h], __shfl_xor_sync(0xffffffffu, mnew[h], 2));
        }
        float corr[2];
        #pragma unroll
        for (int h = 0; h < 2; ++h) {
            float mi = fmaxf(mrun[h], mnew[h]);
            corr[h] = fexp2(mrun[h] - mi);
            mrun[h] = mi;
            lsum[h] *= corr[h];
        }
        float rs[2] = {0.0f, 0.0f};
        #pragma unroll
        for (int nt = 0; nt < 8; ++nt) {
            sacc[nt][0] = fexp2(sacc[nt][0] - mrun[0]);
            sacc[nt][1] = fexp2(sacc[nt][1] - mrun[0]);
            sacc[nt][2] = fexp2(sacc[nt][2] - mrun[1]);
            sacc[nt][3] = fexp2(sacc[nt][3] - mrun[1]);
            rs[0] += sacc[nt][0] + sacc[nt][1];
            rs[1] += sacc[nt][2] + sacc[nt][3];
        }
        #pragma unroll
        for (int h = 0; h < 2; ++h) {
            rs[h] += __shfl_xor_sync(0xffffffffu, rs[h], 1);
            rs[h] += __shfl_xor_sync(0xffffffffu, rs[h], 2);
            lsum[h] += rs[h];
        }
        #pragma unroll
        for (int nt = 0; nt < 8; ++nt) {
            oacc[nt][0] *= corr[0]; oacc[nt][1] *= corr[0];
            oacc[nt][2] *= corr[1]; oacc[nt][3] *= corr[1];
        }

        // ---- O += P V : 1-MMA (P single, V single) ----
        #pragma unroll
        for (int kt = 0; kt < 4; ++kt) {
            uint32_t ph[4];
            ph[0] = packh(sacc[2*kt][0],   sacc[2*kt][1]);
            ph[1] = packh(sacc[2*kt][2],   sacc[2*kt][3]);
            ph[2] = packh(sacc[2*kt+1][0], sacc[2*kt+1][1]);
            ph[3] = packh(sacc[2*kt+1][2], sacc[2*kt+1][3]);
            #pragma unroll
            for (int npp = 0; npp < 4; npp += 2) {
                uint32_t vh[2][4];
                #pragma unroll
                for (int i = 0; i < 2; ++i) {
                    int row = kt * 16 + vR;
                    uint32_t off = (uint32_t)(row * 128)
                                 + (uint32_t)(((((npp + i) * 2 + vC) ^ (row & 7)) << 4));
                    ldm_x4_t(vh[i], vb + off);
                }
                #pragma unroll
                for (int i = 0; i < 2; ++i)
                    #pragma unroll
                    for (int d2 = 0; d2 < 2; ++d2)
                        mma16816(oacc[(npp + i) * 2 + d2], ph,
                                 vh[i][d2*2], vh[i][d2*2+1]);
            }
        }
    }

    // ---- finalize: 1/l, Gram-Schmidt exclusion, fp16 store [b,s,d] ----
    float inv[2] = {1.0f / lsum[0], 1.0f / lsum[1]};
    #pragma unroll
    for (int nt = 0; nt < 8; ++nt) {
        oacc[nt][0] *= inv[0]; oacc[nt][1] *= inv[0];
        oacc[nt][2] *= inv[1]; oacc[nt][3] *= inv[1];
    }

    const int bb = g >> 4, hh = g & 15;
    #pragma unroll
    for (int half = 0; half < 2; ++half) {
        int grow = m0 + wm + (l >> 2) + half * 8;
        const float* vr = VF + gbase + (long)grow * HD_;
        float vv[16];
        float dov = 0.0f, dvv = 0.0f;
        #pragma unroll
        for (int nt = 0; nt < 8; ++nt) {
            float2 t = *(const float2*)(vr + nt * 8 + (l & 3) * 2);
            vv[2*nt] = t.x; vv[2*nt+1] = t.y;
            float o0 = oacc[nt][half*2], o1 = oacc[nt][half*2+1];
            dov += o0 * t.x + o1 * t.y;
            dvv += t.x * t.x + t.y * t.y;
        }
        dov += __shfl_xor_sync(0xffffffffu, dov, 1);
        dov += __shfl_xor_sync(0xffffffffu, dov, 2);
        dvv += __shfl_xor_sync(0xffffffffu, dvv, 1);
        dvv += __shfl_xor_sync(0xffffffffu, dvv, 2);
        float al_ = dov / (dvv + 1e-8f);
        long obase = (long)(bb * S_ + grow) * D_ + hh * HD_;
        #pragma unroll
        for (int nt = 0; nt < 8; ++nt) {
            float rx = oacc[nt][half*2]   - al_ * vv[2*nt];
            float ry = oacc[nt][half*2+1] - al_ * vv[2*nt+1];
            *(uint32_t*)(OBh + obase + nt * 8 + (l & 3) * 2) = packh(rx, ry);
        }
    }
}

// ============================================================================
extern "C" void kernel_launch(void* const* d_in, const int* in_sizes, int n_in,
                              void* d_out, int out_size)
{
    const float* x  = (const float*)d_in[0];
    const float* wq = (const float*)d_in[1];
    const float* bq = (const float*)d_in[2];
    const float* wk = (const float*)d_in[3];
    const float* bk = (const float*)d_in[4];
    const float* wv = (const float*)d_in[5];
    const float* bv = (const float*)d_in[6];
    const float* wo = (const float*)d_in[7];
    const float* bo = (const float*)d_in[8];
    float* out = (float*)d_out;

    __half *xh, *xl, *wh, *wl, *qh, *kh, *kl, *vh, *obh;
    float *vf;
    cudaGetSymbolAddress((void**)&xh,  g_xh);
    cudaGetSymbolAddress((void**)&xl,  g_xl);
    cudaGetSymbolAddress((void**)&wh,  g_wh);
    cudaGetSymbolAddress((void**)&wl,  g_wl);
    cudaGetSymbolAddress((void**)&qh,  g_qh);
    cudaGetSymbolAddress((void**)&kh,  g_kh);
    cudaGetSymbolAddress((void**)&kl,  g_kl);
    cudaGetSymbolAddress((void**)&vh,  g_vh);
    cudaGetSymbolAddress((void**)&vf,  g_vf);
    cudaGetSymbolAddress((void**)&obh, g_obh);

    const int SMG4 = 3 * 32768;    // 98304  (K: 4 planes)
    const int SMG3 = 3 * 24576;    // 73728  (Q: 3 planes)
    const int SMG2 = 3 * 16384;    // 49152  (V, out: 2 planes)
    const int SMF  = 65536;        // Q 16K + K 32K + V 16K
    cudaFuncSetAttribute(gemm_k,   cudaFuncAttributeMaxDynamicSharedMemorySize, SMG4);
    cudaFuncSetAttribute(gemm_q,   cudaFuncAttributeMaxDynamicSharedMemorySize, SMG3);
    cudaFuncSetAttribute(gemm_v,   cudaFuncAttributeMaxDynamicSharedMemorySize, SMG2);
    cudaFuncSetAttribute(gemm_out, cudaFuncAttributeMaxDynamicSharedMemorySize, SMG2);
    cudaFuncSetAttribute(fused_attn, cudaFuncAttributeMaxDynamicSharedMemorySize, SMF);

    // 0) convert x + weights to fp16 hi/lo
    convert_all<<<dim3(512, 8), 256>>>(x, wq, wk, wv, wo, xh, xl, wh, wl);

    // 1) projections: K 3-MMA, Q 2-MMA (pre-scaled), V 1-MMA
    gemm_k<<<dim3(D_/128, M_/128, 1), 256, SMG4>>>(xh, xl, wh, wl, bk, kh, kl);
    gemm_q<<<dim3(D_/128, M_/128, 1), 256, SMG3>>>(xh, xl, wh, bq, qh);
    gemm_v<<<dim3(D_/128, M_/128, 1), 256, SMG2>>>(xh, wh, bv, vh, vf);

    // 2) fused attention + softmax + exclusion -> ob fp16 [b,s,d]
    fused_attn<<<dim3(S_/128, G_), 256, SMF>>>(qh, kh, kl, vh, vf, obh);

    // 3) output projection (1-MMA) -> d_out
    gemm_out<<<dim3(D_/128, M_/128, 1), 256, SMG2>>>(obh, wh, bo, out);
}